// round 5
// baseline (speedup 1.0000x reference)
#include <cuda_runtime.h>
#include <cuda_fp16.h>
#include <cuda_bf16.h>
#include <cstdint>

// self_attention_9225589752302 — round 4: cp.async raw staging to hide LDG phase
// GEMM1 fp16 hi/lo 3-pass split, GEMM2 bf16 hi/lo 3-pass split.
// grid (8 k-tiles, 64 batches), 16 warps = 8 m-strips(16 rows) x 2 j-halves.

#define NTHREADS 512

// smem byte offsets
#define KHI 0u            // K^T [k=128][c=64] fp16, 128B rows, swz ((k&7)<<4)
#define KLO 16384u
#define JHI 32768u        // J [c=64][j=128] fp16, 256B rows, swz ((c&7)<<4)
#define JLO 49152u
#define VHI 65536u        // V [c=64][j=128] bf16
#define VLO 81920u
#define RAWJ 98304u       // raw f32 J tile [64][128] (cp.async dest)
#define RAWV 131072u      // raw f32 V tile [64][128]
#define LRED 163840u      // 384 f32: [0..255] partial row sums, [256..383] 1/l
#define SMEM_BYTES (163840u + 1536u)
#define STAGEOFF RAWJ     // prologue K stage f32 [64][132] (overlaps RAWJ, prologue-only)
#define OSTAGE 0u         // epilogue stage f32 [64][128] (overlaps K tiles, epilogue-only)

static __device__ __forceinline__ uint32_t smem_u32(const void* p) {
    uint32_t a;
    asm("{ .reg .u64 t; cvta.to.shared.u64 t, %1; cvt.u32.u64 %0, t; }" : "=r"(a) : "l"(p));
    return a;
}
static __device__ __forceinline__ void cpa16(uint32_t dst, const void* src) {
    asm volatile("cp.async.cg.shared.global [%0], [%1], 16;" :: "r"(dst), "l"(src));
}
#define CP_COMMIT() asm volatile("cp.async.commit_group;" ::: "memory")
#define CP_WAIT0()  asm volatile("cp.async.wait_group 0;" ::: "memory")

static __device__ __forceinline__ void ldsm4(uint32_t r[4], uint32_t a) {
    asm volatile("ldmatrix.sync.aligned.m8n8.x4.shared.b16 {%0,%1,%2,%3}, [%4];"
        : "=r"(r[0]), "=r"(r[1]), "=r"(r[2]), "=r"(r[3]) : "r"(a));
}
static __device__ __forceinline__ void ldsm4t(uint32_t r[4], uint32_t a) {
    asm volatile("ldmatrix.sync.aligned.m8n8.x4.trans.shared.b16 {%0,%1,%2,%3}, [%4];"
        : "=r"(r[0]), "=r"(r[1]), "=r"(r[2]), "=r"(r[3]) : "r"(a));
}
static __device__ __forceinline__ void mma_f16(float d[4], const uint32_t a[4], uint32_t b0, uint32_t b1) {
    asm("mma.sync.aligned.m16n8k16.row.col.f32.f16.f16.f32 "
        "{%0,%1,%2,%3}, {%4,%5,%6,%7}, {%8,%9}, {%0,%1,%2,%3};"
        : "+f"(d[0]), "+f"(d[1]), "+f"(d[2]), "+f"(d[3])
        : "r"(a[0]), "r"(a[1]), "r"(a[2]), "r"(a[3]), "r"(b0), "r"(b1));
}
static __device__ __forceinline__ void mma_bf16(float d[4], const uint32_t a[4], uint32_t b0, uint32_t b1) {
    asm("mma.sync.aligned.m16n8k16.row.col.f32.bf16.bf16.f32 "
        "{%0,%1,%2,%3}, {%4,%5,%6,%7}, {%8,%9}, {%0,%1,%2,%3};"
        : "+f"(d[0]), "+f"(d[1]), "+f"(d[2]), "+f"(d[3])
        : "r"(a[0]), "r"(a[1]), "r"(a[2]), "r"(a[3]), "r"(b0), "r"(b1));
}
static __device__ __forceinline__ uint32_t u32h2(__half2 h)         { return *(uint32_t*)&h; }
static __device__ __forceinline__ uint32_t u32b2(__nv_bfloat162 h)  { return *(uint32_t*)&h; }

__global__ __launch_bounds__(NTHREADS, 1)
void attn_mma_kernel(const float* __restrict__ Kg, const float* __restrict__ Jg,
                     const float* __restrict__ Vg, float* __restrict__ Og) {
    extern __shared__ char smem[];
    const uint32_t smb = smem_u32(smem);
    float* stage = (float*)(smem + STAGEOFF);
    float* lred  = (float*)(smem + LRED);
    float* ostage = (float*)(smem + OSTAGE);

    const int tid  = threadIdx.x;
    const int lane = tid & 31;
    const int wid  = tid >> 5;
    const int wm   = wid & 7;      // m-strip: rows 16*wm..+15
    const int wn   = wid >> 3;     // j-half: 64*wn..+63
    const int m0   = wm * 16;
    const int j0   = wn * 64;
    const unsigned base  = (unsigned)blockIdx.y * 65536u;
    const unsigned kbase = (unsigned)blockIdx.x * 128u;

    // per-thread copy/convert coordinates (same mapping for cp.async and convert)
    int cc[4], cj4[4];
    uint32_t rawoff[4];
    #pragma unroll
    for (int t = 0; t < 4; t++) {
        int flat = tid + t * NTHREADS;
        cc[t] = flat >> 5; cj4[t] = flat & 31;
        rawoff[t] = ((uint32_t)cc[t] * 128u + (uint32_t)cj4[t] * 4u) * 4u;
    }

    // ---------- Prologue: K^T tile (transpose + fp16 hi/lo split) ----------
    #pragma unroll
    for (int t = 0; t < 4; t++) {
        float4 v = *(const float4*)(Kg + base + (unsigned)cc[t] * 1024u + kbase + cj4[t] * 4);
        float* s = stage + cc[t] * 132 + cj4[t] * 4;
        s[0] = v.x; s[1] = v.y; s[2] = v.z; s[3] = v.w;
    }
    __syncthreads();
    #pragma unroll
    for (int t = 0; t < 8; t++) {
        int flat = tid + t * NTHREADS;
        int c = (flat & 31) * 2, k = flat >> 5;
        float x0 = stage[c * 132 + k], x1 = stage[(c + 1) * 132 + k];
        __half2 h = __floats2half2_rn(x0, x1);
        float2 hb = __half22float2(h);
        __half2 l = __floats2half2_rn(x0 - hb.x, x1 - hb.y);
        uint32_t off = (uint32_t)k * 128u + ((((uint32_t)c) * 2u) ^ ((((uint32_t)k) & 7u) << 4));
        *(uint32_t*)(smem + KHI + off) = u32h2(h);
        *(uint32_t*)(smem + KLO + off) = u32h2(l);
    }
    __syncthreads();   // stage reads done before cp.async overwrites RAWJ

    // issue cp.async for tile 0
    #pragma unroll
    for (int t = 0; t < 4; t++) {
        unsigned g = base + (unsigned)cc[t] * 1024u + (unsigned)cj4[t] * 4u;
        cpa16(smb + RAWJ + rawoff[t], Jg + g);
        cpa16(smb + RAWV + rawoff[t], Vg + g);
    }
    CP_COMMIT();

    float D2[8][4];
    #pragma unroll
    for (int nt = 0; nt < 8; nt++)
        #pragma unroll
        for (int i = 0; i < 4; i++) D2[nt][i] = 0.0f;
    float rsum[2] = {0.0f, 0.0f};

    // lane-constant address pieces
    const uint32_t xorl  = (uint32_t)(lane & 7) << 4;
    const uint32_t aRow0 = (uint32_t)(m0 + (lane & 15)) * 128u;
    const uint32_t aColH = (uint32_t)((lane >> 4) << 4);
    const uint32_t bRowJ = (uint32_t)((lane & 15)) * 256u;
    const uint32_t bColJ = (uint32_t)((lane >> 4) << 4);
    const uint32_t vRow  = (uint32_t)(lane & 7) * 256u;
    const uint32_t vColH = (uint32_t)((lane >> 3) << 4);

    for (int jt = 0; jt < 8; jt++) {
        // ---------- convert raw (own float4s only) -> fp16/bf16 hi/lo smem ----------
        CP_WAIT0();
        #pragma unroll
        for (int t = 0; t < 4; t++) {
            int c = cc[t], j4 = cj4[t];
            uint32_t soff = (uint32_t)c * 256u + ((((uint32_t)j4) * 8u) ^ ((((uint32_t)c) & 7u) << 4));
            float4 jv = *(const float4*)(smem + RAWJ + rawoff[t]);
            __half2 jh0 = __floats2half2_rn(jv.x, jv.y), jh1 = __floats2half2_rn(jv.z, jv.w);
            float2 f0 = __half22float2(jh0), f1 = __half22float2(jh1);
            __half2 jl0 = __floats2half2_rn(jv.x - f0.x, jv.y - f0.y);
            __half2 jl1 = __floats2half2_rn(jv.z - f1.x, jv.w - f1.y);
            *(uint2*)(smem + JHI + soff) = make_uint2(u32h2(jh0), u32h2(jh1));
            *(uint2*)(smem + JLO + soff) = make_uint2(u32h2(jl0), u32h2(jl1));
            float4 vv = *(const float4*)(smem + RAWV + rawoff[t]);
            __nv_bfloat162 vh0 = __floats2bfloat162_rn(vv.x, vv.y), vh1 = __floats2bfloat162_rn(vv.z, vv.w);
            float2 g0 = __bfloat1622float2(vh0), g1 = __bfloat1622float2(vh1);
            __nv_bfloat162 vl0 = __floats2bfloat162_rn(vv.x - g0.x, vv.y - g0.y);
            __nv_bfloat162 vl1 = __floats2bfloat162_rn(vv.z - g1.x, vv.w - g1.y);
            *(uint2*)(smem + VHI + soff) = make_uint2(u32b2(vh0), u32b2(vh1));
            *(uint2*)(smem + VLO + soff) = make_uint2(u32b2(vl0), u32b2(vl1));
        }
        __syncthreads();

        // ---------- prefetch next tile (overlaps GEMMs) ----------
        if (jt < 7) {
            #pragma unroll
            for (int t = 0; t < 4; t++) {
                unsigned g = base + (unsigned)cc[t] * 1024u + (unsigned)(jt + 1) * 128u + (unsigned)cj4[t] * 4u;
                cpa16(smb + RAWJ + rawoff[t], Jg + g);
                cpa16(smb + RAWV + rawoff[t], Vg + g);
            }
            CP_COMMIT();
        }

        #pragma unroll
        for (int h = 0; h < 2; h++) {
            // ---------- GEMM1: S[16 x 32] for this j-quarter (h) ----------
            float S[4][4];
            #pragma unroll
            for (int nt = 0; nt < 4; nt++)
                #pragma unroll
                for (int i = 0; i < 4; i++) S[nt][i] = 0.0f;

            #pragma unroll
            for (int ks = 0; ks < 4; ks++) {
                uint32_t ah[4], al[4];
                uint32_t acol = ((uint32_t)(ks * 32) + aColH) ^ xorl;
                ldsm4(ah, smb + KHI + aRow0 + acol);
                ldsm4(al, smb + KLO + aRow0 + acol);
                uint32_t jrow = (uint32_t)(ks * 16) * 256u + bRowJ;
                #pragma unroll
                for (int ntp = 0; ntp < 2; ntp++) {
                    uint32_t bh[4], bl[4];
                    uint32_t bcol = ((uint32_t)((j0 + h * 32 + ntp * 16) * 2) + bColJ) ^ xorl;
                    ldsm4t(bh, smb + JHI + jrow + bcol);
                    ldsm4t(bl, smb + JLO + jrow + bcol);
                    #pragma unroll
                    for (int q = 0; q < 2; q++) {
                        int nt = 2 * ntp + q;
                        mma_f16(S[nt], ah, bh[2 * q], bh[2 * q + 1]);
                        mma_f16(S[nt], ah, bl[2 * q], bl[2 * q + 1]);
                        mma_f16(S[nt], al, bh[2 * q], bh[2 * q + 1]);
                    }
                }
            }

            // ---------- softmax: P = exp(S), bf16 hi/lo A-fragments ----------
            uint32_t phi[2][4], plo[2][4];
            #pragma unroll
            for (int kl = 0; kl < 2; kl++)
                #pragma unroll
                for (int q = 0; q < 2; q++) {
                    const float* s = S[2 * kl + q];
                    float p0 = __expf(s[0]), p1 = __expf(s[1]);
                    float p2 = __expf(s[2]), p3 = __expf(s[3]);
                    rsum[0] += p0 + p1;
                    rsum[1] += p2 + p3;
                    __nv_bfloat162 h01 = __floats2bfloat162_rn(p0, p1);
                    __nv_bfloat162 h23 = __floats2bfloat162_rn(p2, p3);
                    float2 b01 = __bfloat1622float2(h01), b23 = __bfloat1622float2(h23);
                    __nv_bfloat162 l01 = __floats2bfloat162_rn(p0 - b01.x, p1 - b01.y);
                    __nv_bfloat162 l23 = __floats2bfloat162_rn(p2 - b23.x, p3 - b23.y);
                    phi[kl][2 * q]     = u32b2(h01);
                    phi[kl][2 * q + 1] = u32b2(h23);
                    plo[kl][2 * q]     = u32b2(l01);
                    plo[kl][2 * q + 1] = u32b2(l23);
                }

            // ---------- GEMM2: D2 += P x V^T over this half's j ----------
            uint32_t vcol = ((uint32_t)((j0 + h * 32) * 2) + vColH) ^ xorl;
            #pragma unroll
            for (int nt = 0; nt < 8; nt++) {
                uint32_t bh[4], bl[4];
                uint32_t vr = (uint32_t)(nt * 8) * 256u + vRow;
                ldsm4(bh, smb + VHI + vr + vcol);
                ldsm4(bl, smb + VLO + vr + vcol);
                #pragma unroll
                for (int kl = 0; kl < 2; kl++) {
                    mma_bf16(D2[nt], phi[kl], bh[2 * kl], bh[2 * kl + 1]);
                    mma_bf16(D2[nt], phi[kl], bl[2 * kl], bl[2 * kl + 1]);
                    mma_bf16(D2[nt], plo[kl], bh[2 * kl], bh[2 * kl + 1]);
                }
            }
        }
        __syncthreads();   // all warps done reading conv buffers before next convert
    }

    // ---------- Epilogue ----------
    #pragma unroll
    for (int rr = 0; rr < 2; rr++) {
        float v = rsum[rr];
        v += __shfl_xor_sync(0xffffffffu, v, 1);
        v += __shfl_xor_sync(0xffffffffu, v, 2);
        if ((lane & 3) == 0)
            lred[wn * 128 + m0 + rr * 8 + (lane >> 2)] = v;
    }
    __syncthreads();
    if (tid < 128) lred[256 + tid] = 1.0f / (lred[tid] + lred[128 + tid]);

    if (wn == 0) {
        #pragma unroll
        for (int nt = 0; nt < 8; nt++) {
            int c0 = nt * 8 + 2 * (lane & 3);
            int r = m0 + (lane >> 2);
            ostage[c0 * 128 + r]           = D2[nt][0];
            ostage[(c0 + 1) * 128 + r]     = D2[nt][1];
            ostage[c0 * 128 + r + 8]       = D2[nt][2];
            ostage[(c0 + 1) * 128 + r + 8] = D2[nt][3];
        }
    }
    __syncthreads();
    if (wn == 1) {
        #pragma unroll
        for (int nt = 0; nt < 8; nt++) {
            int c0 = nt * 8 + 2 * (lane & 3);
            int r = m0 + (lane >> 2);
            ostage[c0 * 128 + r]           += D2[nt][0];
            ostage[(c0 + 1) * 128 + r]     += D2[nt][1];
            ostage[c0 * 128 + r + 8]       += D2[nt][2];
            ostage[(c0 + 1) * 128 + r + 8] += D2[nt][3];
        }
    }
    __syncthreads();

    #pragma unroll
    for (int t = 0; t < 4; t++) {
        int c = cc[t], k4 = cj4[t];
        float4 v  = *(float4*)(ostage + c * 128 + k4 * 4);
        float4 iv = *(float4*)(lred + 256 + k4 * 4);
        v.x *= iv.x; v.y *= iv.y; v.z *= iv.z; v.w *= iv.w;
        *(float4*)(Og + base + (unsigned)c * 1024u + kbase + (unsigned)k4 * 4u) = v;
    }
}

extern "C" void kernel_launch(void* const* d_in, const int* in_sizes, int n_in,
                              void* d_out, int out_size) {
    const float* Kg = (const float*)d_in[0];
    const float* Jg = (const float*)d_in[1];
    const float* Vg = (const float*)d_in[2];
    float* Og = (float*)d_out;

    cudaFuncSetAttribute(attn_mma_kernel,
                         cudaFuncAttributeMaxDynamicSharedMemorySize, SMEM_BYTES);
    dim3 grid(8, 64);
    attn_mma_kernel<<<grid, NTHREADS, SMEM_BYTES>>>(Kg, Jg, Vg, Og);
}

// round 6
// speedup vs baseline: 1.0789x; 1.0789x over previous
#include <cuda_runtime.h>
#include <cuda_fp16.h>
#include <cuda_bf16.h>
#include <cstdint>

// self_attention_9225589752302 — round 5: reg-prefetch + split converts + merged-h GEMMs
// GEMM1 fp16 hi/lo 3-pass split, GEMM2 bf16 hi/lo 3-pass split.
// grid (8 k-tiles, 64 batches), 16 warps = 8 m-strips(16 rows) x 2 j-halves.

#define NTHREADS 512

// smem byte offsets
#define KHI 0u            // K^T [k=128][c=64] fp16, 128B rows, swz ((k&7)<<4)
#define KLO 16384u
#define JHI 32768u        // J [c=64][j=128] fp16, 256B rows, swz ((c&7)<<4)
#define JLO 49152u
#define VHI 65536u        // V [c=64][j=128] bf16
#define VLO 81920u
#define LRED 98304u       // 384 f32: [0..255] partial row sums, [256..383] 1/l
#define SMEM_BYTES (98304u + 1536u)
#define STAGEOFF JHI      // prologue K stage f32 [64][132] (overlaps J/V hi, prologue-only)
#define OSTAGE 0u         // epilogue stage f32 [64][128] (overlaps K tiles, epilogue-only)

static __device__ __forceinline__ uint32_t smem_u32(const void* p) {
    uint32_t a;
    asm("{ .reg .u64 t; cvta.to.shared.u64 t, %1; cvt.u32.u64 %0, t; }" : "=r"(a) : "l"(p));
    return a;
}
static __device__ __forceinline__ void ldsm4(uint32_t r[4], uint32_t a) {
    asm volatile("ldmatrix.sync.aligned.m8n8.x4.shared.b16 {%0,%1,%2,%3}, [%4];"
        : "=r"(r[0]), "=r"(r[1]), "=r"(r[2]), "=r"(r[3]) : "r"(a));
}
static __device__ __forceinline__ void ldsm4t(uint32_t r[4], uint32_t a) {
    asm volatile("ldmatrix.sync.aligned.m8n8.x4.trans.shared.b16 {%0,%1,%2,%3}, [%4];"
        : "=r"(r[0]), "=r"(r[1]), "=r"(r[2]), "=r"(r[3]) : "r"(a));
}
static __device__ __forceinline__ void mma_f16(float d[4], const uint32_t a[4], uint32_t b0, uint32_t b1) {
    asm("mma.sync.aligned.m16n8k16.row.col.f32.f16.f16.f32 "
        "{%0,%1,%2,%3}, {%4,%5,%6,%7}, {%8,%9}, {%0,%1,%2,%3};"
        : "+f"(d[0]), "+f"(d[1]), "+f"(d[2]), "+f"(d[3])
        : "r"(a[0]), "r"(a[1]), "r"(a[2]), "r"(a[3]), "r"(b0), "r"(b1));
}
static __device__ __forceinline__ void mma_bf16(float d[4], const uint32_t a[4], uint32_t b0, uint32_t b1) {
    asm("mma.sync.aligned.m16n8k16.row.col.f32.bf16.bf16.f32 "
        "{%0,%1,%2,%3}, {%4,%5,%6,%7}, {%8,%9}, {%0,%1,%2,%3};"
        : "+f"(d[0]), "+f"(d[1]), "+f"(d[2]), "+f"(d[3])
        : "r"(a[0]), "r"(a[1]), "r"(a[2]), "r"(a[3]), "r"(b0), "r"(b1));
}
static __device__ __forceinline__ uint32_t u32h2(__half2 h)         { return *(uint32_t*)&h; }
static __device__ __forceinline__ uint32_t u32b2(__nv_bfloat162 h)  { return *(uint32_t*)&h; }

__global__ __launch_bounds__(NTHREADS, 1)
void attn_mma_kernel(const float* __restrict__ Kg, const float* __restrict__ Jg,
                     const float* __restrict__ Vg, float* __restrict__ Og) {
    extern __shared__ char smem[];
    const uint32_t smb = smem_u32(smem);
    float* stage = (float*)(smem + STAGEOFF);
    float* lred  = (float*)(smem + LRED);
    float* ostage = (float*)(smem + OSTAGE);

    const int tid  = threadIdx.x;
    const int lane = tid & 31;
    const int wid  = tid >> 5;
    const int wm   = wid & 7;      // m-strip: rows 16*wm..+15
    const int wn   = wid >> 3;     // j-half: 64*wn..+63
    const int m0   = wm * 16;
    const int j0   = wn * 64;
    const unsigned base  = (unsigned)blockIdx.y * 65536u;
    const unsigned kbase = (unsigned)blockIdx.x * 128u;

    // per-thread copy/convert coordinates
    int cc[4], cj4[4];
    uint32_t soffs[4];
    unsigned goffs[4];
    #pragma unroll
    for (int t = 0; t < 4; t++) {
        int flat = tid + t * NTHREADS;
        cc[t] = flat >> 5; cj4[t] = flat & 31;
        soffs[t] = (uint32_t)cc[t] * 256u + ((((uint32_t)cj4[t]) * 8u) ^ ((((uint32_t)cc[t]) & 7u) << 4));
        goffs[t] = base + (unsigned)cc[t] * 1024u + (unsigned)cj4[t] * 4u;
    }

    // prefetch J tile 0 into registers (in flight during prologue)
    float4 jreg[4];
    #pragma unroll
    for (int t = 0; t < 4; t++) jreg[t] = *(const float4*)(Jg + goffs[t]);

    // ---------- Prologue: K^T tile (transpose + fp16 hi/lo split) ----------
    #pragma unroll
    for (int t = 0; t < 4; t++) {
        float4 v = *(const float4*)(Kg + base + (unsigned)cc[t] * 1024u + kbase + cj4[t] * 4);
        float* s = stage + cc[t] * 132 + cj4[t] * 4;
        s[0] = v.x; s[1] = v.y; s[2] = v.z; s[3] = v.w;
    }
    __syncthreads();
    #pragma unroll
    for (int t = 0; t < 8; t++) {
        int flat = tid + t * NTHREADS;
        int c = (flat & 31) * 2, k = flat >> 5;
        float x0 = stage[c * 132 + k], x1 = stage[(c + 1) * 132 + k];
        __half2 h = __floats2half2_rn(x0, x1);
        float2 hb = __half22float2(h);
        __half2 l = __floats2half2_rn(x0 - hb.x, x1 - hb.y);
        uint32_t off = (uint32_t)k * 128u + ((((uint32_t)c) * 2u) ^ ((((uint32_t)k) & 7u) << 4));
        *(uint32_t*)(smem + KHI + off) = u32h2(h);
        *(uint32_t*)(smem + KLO + off) = u32h2(l);
    }
    __syncthreads();   // stage (J region) reads done before J convert writes

    float D2[8][4];
    #pragma unroll
    for (int nt = 0; nt < 8; nt++)
        #pragma unroll
        for (int i = 0; i < 4; i++) D2[nt][i] = 0.0f;
    float rsum[2] = {0.0f, 0.0f};

    // lane-constant address pieces
    const uint32_t xorl  = (uint32_t)(lane & 7) << 4;
    const uint32_t aRow0 = (uint32_t)(m0 + (lane & 15)) * 128u;
    const uint32_t aColH = (uint32_t)((lane >> 4) << 4);
    const uint32_t bRowJ = (uint32_t)((lane & 15)) * 256u;
    const uint32_t bColJ = (uint32_t)((lane >> 4) << 4);
    const uint32_t vRow  = (uint32_t)(lane & 7) * 256u;
    const uint32_t vColH = (uint32_t)((lane >> 3) << 4);
    const uint32_t vcol0 = ((uint32_t)(j0 * 2)        + vColH) ^ xorl;
    const uint32_t vcol1 = ((uint32_t)((j0 + 32) * 2) + vColH) ^ xorl;

    for (int jt = 0; jt < 8; jt++) {
        // ---------- convert J (from prefetched regs) -> fp16 hi/lo smem ----------
        #pragma unroll
        for (int t = 0; t < 4; t++) {
            float4 jv = jreg[t];
            __half2 jh0 = __floats2half2_rn(jv.x, jv.y), jh1 = __floats2half2_rn(jv.z, jv.w);
            float2 f0 = __half22float2(jh0), f1 = __half22float2(jh1);
            __half2 jl0 = __floats2half2_rn(jv.x - f0.x, jv.y - f0.y);
            __half2 jl1 = __floats2half2_rn(jv.z - f1.x, jv.w - f1.y);
            *(uint2*)(smem + JHI + soffs[t]) = make_uint2(u32h2(jh0), u32h2(jh1));
            *(uint2*)(smem + JLO + soffs[t]) = make_uint2(u32h2(jl0), u32h2(jl1));
        }
        // issue V loads (in flight during GEMM1)
        float4 vreg[4];
        #pragma unroll
        for (int t = 0; t < 4; t++)
            vreg[t] = *(const float4*)(Vg + goffs[t] + (unsigned)jt * 128u);
        __syncthreads();

        // ---------- GEMM1: S[16 x 64] merged over both 32-col halves ----------
        float S[8][4];
        #pragma unroll
        for (int nt = 0; nt < 8; nt++)
            #pragma unroll
            for (int i = 0; i < 4; i++) S[nt][i] = 0.0f;

        #pragma unroll
        for (int ks = 0; ks < 4; ks++) {
            uint32_t ah[4], al[4];
            uint32_t acol = ((uint32_t)(ks * 32) + aColH) ^ xorl;
            ldsm4(ah, smb + KHI + aRow0 + acol);
            ldsm4(al, smb + KLO + aRow0 + acol);
            uint32_t jrow = (uint32_t)(ks * 16) * 256u + bRowJ;
            #pragma unroll
            for (int ntp = 0; ntp < 4; ntp++) {
                uint32_t bh[4], bl[4];
                uint32_t bcol = ((uint32_t)((j0 + ntp * 16) * 2) + bColJ) ^ xorl;
                ldsm4t(bh, smb + JHI + jrow + bcol);
                ldsm4t(bl, smb + JLO + jrow + bcol);
                #pragma unroll
                for (int q = 0; q < 2; q++) {
                    int nt = 2 * ntp + q;
                    mma_f16(S[nt], ah, bh[2 * q], bh[2 * q + 1]);
                    mma_f16(S[nt], ah, bl[2 * q], bl[2 * q + 1]);
                    mma_f16(S[nt], al, bh[2 * q], bh[2 * q + 1]);
                }
            }
        }

        // ---------- softmax: P = exp(S), bf16 hi/lo A-fragments (4 j-groups) ----------
        uint32_t phi[4][4], plo[4][4];
        #pragma unroll
        for (int g = 0; g < 4; g++)
            #pragma unroll
            for (int q = 0; q < 2; q++) {
                const float* s = S[2 * g + q];
                float p0 = __expf(s[0]), p1 = __expf(s[1]);
                float p2 = __expf(s[2]), p3 = __expf(s[3]);
                rsum[0] += p0 + p1;
                rsum[1] += p2 + p3;
                __nv_bfloat162 h01 = __floats2bfloat162_rn(p0, p1);
                __nv_bfloat162 h23 = __floats2bfloat162_rn(p2, p3);
                float2 b01 = __bfloat1622float2(h01), b23 = __bfloat1622float2(h23);
                __nv_bfloat162 l01 = __floats2bfloat162_rn(p0 - b01.x, p1 - b01.y);
                __nv_bfloat162 l23 = __floats2bfloat162_rn(p2 - b23.x, p3 - b23.y);
                phi[g][2 * q]     = u32b2(h01);
                phi[g][2 * q + 1] = u32b2(h23);
                plo[g][2 * q]     = u32b2(l01);
                plo[g][2 * q + 1] = u32b2(l23);
            }

        // ---------- convert V (from regs) -> bf16 hi/lo smem ----------
        #pragma unroll
        for (int t = 0; t < 4; t++) {
            float4 vv = vreg[t];
            __nv_bfloat162 vh0 = __floats2bfloat162_rn(vv.x, vv.y), vh1 = __floats2bfloat162_rn(vv.z, vv.w);
            float2 g0 = __bfloat1622float2(vh0), g1 = __bfloat1622float2(vh1);
            __nv_bfloat162 vl0 = __floats2bfloat162_rn(vv.x - g0.x, vv.y - g0.y);
            __nv_bfloat162 vl1 = __floats2bfloat162_rn(vv.z - g1.x, vv.w - g1.y);
            *(uint2*)(smem + VHI + soffs[t]) = make_uint2(u32b2(vh0), u32b2(vh1));
            *(uint2*)(smem + VLO + soffs[t]) = make_uint2(u32b2(vl0), u32b2(vl1));
        }
        __syncthreads();

        // prefetch J for next iter (in flight during GEMM2)
        if (jt < 7) {
            #pragma unroll
            for (int t = 0; t < 4; t++)
                jreg[t] = *(const float4*)(Jg + goffs[t] + (unsigned)(jt + 1) * 128u);
        }

        // ---------- GEMM2: D2 += P x V^T over full 64-j half ----------
        #pragma unroll
        for (int nt = 0; nt < 8; nt++) {
            uint32_t bh0[4], bh1[4], bl0[4], bl1[4];
            uint32_t vr = (uint32_t)(nt * 8) * 256u + vRow;
            ldsm4(bh0, smb + VHI + vr + vcol0);
            ldsm4(bh1, smb + VHI + vr + vcol1);
            ldsm4(bl0, smb + VLO + vr + vcol0);
            ldsm4(bl1, smb + VLO + vr + vcol1);
            #pragma unroll
            for (int g = 0; g < 4; g++) {
                const uint32_t* bh = (g < 2) ? bh0 : bh1;
                const uint32_t* bl = (g < 2) ? bl0 : bl1;
                int kk = 2 * (g & 1);
                mma_bf16(D2[nt], phi[g], bh[kk], bh[kk + 1]);
                mma_bf16(D2[nt], phi[g], bl[kk], bl[kk + 1]);
                mma_bf16(D2[nt], plo[g], bh[kk], bh[kk + 1]);
            }
        }
    }

    // ---------- Epilogue ----------
    #pragma unroll
    for (int rr = 0; rr < 2; rr++) {
        float v = rsum[rr];
        v += __shfl_xor_sync(0xffffffffu, v, 1);
        v += __shfl_xor_sync(0xffffffffu, v, 2);
        if ((lane & 3) == 0)
            lred[wn * 128 + m0 + rr * 8 + (lane >> 2)] = v;
    }
    __syncthreads();
    if (tid < 128) lred[256 + tid] = 1.0f / (lred[tid] + lred[128 + tid]);

    if (wn == 0) {
        #pragma unroll
        for (int nt = 0; nt < 8; nt++) {
            int c0 = nt * 8 + 2 * (lane & 3);
            int r = m0 + (lane >> 2);
            ostage[c0 * 128 + r]           = D2[nt][0];
            ostage[(c0 + 1) * 128 + r]     = D2[nt][1];
            ostage[c0 * 128 + r + 8]       = D2[nt][2];
            ostage[(c0 + 1) * 128 + r + 8] = D2[nt][3];
        }
    }
    __syncthreads();
    if (wn == 1) {
        #pragma unroll
        for (int nt = 0; nt < 8; nt++) {
            int c0 = nt * 8 + 2 * (lane & 3);
            int r = m0 + (lane >> 2);
            ostage[c0 * 128 + r]           += D2[nt][0];
            ostage[(c0 + 1) * 128 + r]     += D2[nt][1];
            ostage[c0 * 128 + r + 8]       += D2[nt][2];
            ostage[(c0 + 1) * 128 + r + 8] += D2[nt][3];
        }
    }
    __syncthreads();

    #pragma unroll
    for (int t = 0; t < 4; t++) {
        int c = cc[t], k4 = cj4[t];
        float4 v  = *(float4*)(ostage + c * 128 + k4 * 4);
        float4 iv = *(float4*)(lred + 256 + k4 * 4);
        v.x *= iv.x; v.y *= iv.y; v.z *= iv.z; v.w *= iv.w;
        *(float4*)(Og + base + (unsigned)c * 1024u + kbase + (unsigned)k4 * 4u) = v;
    }
}

extern "C" void kernel_launch(void* const* d_in, const int* in_sizes, int n_in,
                              void* d_out, int out_size) {
    const float* Kg = (const float*)d_in[0];
    const float* Jg = (const float*)d_in[1];
    const float* Vg = (const float*)d_in[2];
    float* Og = (float*)d_out;

    cudaFuncSetAttribute(attn_mma_kernel,
                         cudaFuncAttributeMaxDynamicSharedMemorySize, SMEM_BYTES);
    dim3 grid(8, 64);
    attn_mma_kernel<<<grid, NTHREADS, SMEM_BYTES>>>(Kg, Jg, Vg, Og);
}

// round 7
// speedup vs baseline: 1.2131x; 1.1244x over previous
#include <cuda_runtime.h>
#include <cuda_fp16.h>
#include <cuda_bf16.h>
#include <cstdint>

// self_attention_9225589752302 — round 6: BK=64/BJ=64 small tiles, 2 CTAs/SM
// GEMM1 fp16 hi/lo 3-pass split, GEMM2 bf16 hi/lo 3-pass split.
// grid (16 k-tiles, 64 batches), 256 thr = 8 warps: 4 m-strips(16) x 2 j-halves(32).

#define NTHREADS 256

// smem byte offsets (per 49KB CTA)
#define KHI 0u            // K^T [k=64][c=64] fp16, 128B rows, swz ((k&7)<<4)
#define KLO 8192u
#define JHI 16384u        // J [c=64][j=64] fp16, 128B rows, swz ((c&7)<<4)
#define JLO 24576u
#define VHI 32768u        // V [c=64][j=64] bf16, 128B rows
#define VLO 40960u
#define LRED 49152u       // 192 f32: [0..127] partial row sums, [128..191] 1/l
#define SMEM_BYTES (49152u + 1024u)
#define STAGEOFF JHI      // prologue K stage f32 [64][68] (17.4KB, overlaps J region)
#define OSTAGE 0u         // epilogue stage f32 [64][64] (16KB, overlaps K tiles)

static __device__ __forceinline__ uint32_t smem_u32(const void* p) {
    uint32_t a;
    asm("{ .reg .u64 t; cvta.to.shared.u64 t, %1; cvt.u32.u64 %0, t; }" : "=r"(a) : "l"(p));
    return a;
}
static __device__ __forceinline__ void ldsm4(uint32_t r[4], uint32_t a) {
    asm volatile("ldmatrix.sync.aligned.m8n8.x4.shared.b16 {%0,%1,%2,%3}, [%4];"
        : "=r"(r[0]), "=r"(r[1]), "=r"(r[2]), "=r"(r[3]) : "r"(a));
}
static __device__ __forceinline__ void ldsm4t(uint32_t r[4], uint32_t a) {
    asm volatile("ldmatrix.sync.aligned.m8n8.x4.trans.shared.b16 {%0,%1,%2,%3}, [%4];"
        : "=r"(r[0]), "=r"(r[1]), "=r"(r[2]), "=r"(r[3]) : "r"(a));
}
static __device__ __forceinline__ void mma_f16(float d[4], const uint32_t a[4], uint32_t b0, uint32_t b1) {
    asm("mma.sync.aligned.m16n8k16.row.col.f32.f16.f16.f32 "
        "{%0,%1,%2,%3}, {%4,%5,%6,%7}, {%8,%9}, {%0,%1,%2,%3};"
        : "+f"(d[0]), "+f"(d[1]), "+f"(d[2]), "+f"(d[3])
        : "r"(a[0]), "r"(a[1]), "r"(a[2]), "r"(a[3]), "r"(b0), "r"(b1));
}
static __device__ __forceinline__ void mma_bf16(float d[4], const uint32_t a[4], uint32_t b0, uint32_t b1) {
    asm("mma.sync.aligned.m16n8k16.row.col.f32.bf16.bf16.f32 "
        "{%0,%1,%2,%3}, {%4,%5,%6,%7}, {%8,%9}, {%0,%1,%2,%3};"
        : "+f"(d[0]), "+f"(d[1]), "+f"(d[2]), "+f"(d[3])
        : "r"(a[0]), "r"(a[1]), "r"(a[2]), "r"(a[3]), "r"(b0), "r"(b1));
}
static __device__ __forceinline__ uint32_t u32h2(__half2 h)         { return *(uint32_t*)&h; }
static __device__ __forceinline__ uint32_t u32b2(__nv_bfloat162 h)  { return *(uint32_t*)&h; }

__global__ __launch_bounds__(NTHREADS, 2)
void attn_mma_kernel(const float* __restrict__ Kg, const float* __restrict__ Jg,
                     const float* __restrict__ Vg, float* __restrict__ Og) {
    extern __shared__ char smem[];
    const uint32_t smb = smem_u32(smem);
    float* stage = (float*)(smem + STAGEOFF);
    float* lred  = (float*)(smem + LRED);
    float* ostage = (float*)(smem + OSTAGE);

    const int tid  = threadIdx.x;
    const int lane = tid & 31;
    const int wid  = tid >> 5;
    const int wm   = wid & 3;      // m-strip: rows 16*wm..+15 (of 64)
    const int wn   = wid >> 2;     // j-half: 32*wn..+31 (of 64)
    const int m0   = wm * 16;
    const int j0   = wn * 32;
    const unsigned base  = (unsigned)blockIdx.y * 65536u;
    const unsigned kbase = (unsigned)blockIdx.x * 64u;

    // per-thread copy/convert coordinates: 64c x 16 float4 = 1024 float4 / 256 thr = 4 each
    int cc[4], cj4[4];
    uint32_t soffs[4];
    unsigned goffs[4];
    #pragma unroll
    for (int t = 0; t < 4; t++) {
        int flat = tid + t * NTHREADS;
        cc[t] = flat >> 4; cj4[t] = flat & 15;
        soffs[t] = (uint32_t)cc[t] * 128u + ((((uint32_t)cj4[t]) * 8u) ^ ((((uint32_t)cc[t]) & 7u) << 4));
        goffs[t] = base + (unsigned)cc[t] * 1024u + (unsigned)cj4[t] * 4u;
    }

    // prefetch J tile 0 into registers
    float4 jreg[4];
    #pragma unroll
    for (int t = 0; t < 4; t++) jreg[t] = *(const float4*)(Jg + goffs[t]);

    // ---------- Prologue: K^T tile (transpose + fp16 hi/lo split) ----------
    #pragma unroll
    for (int t = 0; t < 4; t++) {
        float4 v = *(const float4*)(Kg + base + (unsigned)cc[t] * 1024u + kbase + cj4[t] * 4);
        float* s = stage + cc[t] * 68 + cj4[t] * 4;
        s[0] = v.x; s[1] = v.y; s[2] = v.z; s[3] = v.w;
    }
    __syncthreads();
    #pragma unroll
    for (int t = 0; t < 8; t++) {
        int flat = tid + t * NTHREADS;       // [0,2048): k=flat>>5, c-pair=(flat&31)*2
        int c = (flat & 31) * 2, k = flat >> 5;
        float x0 = stage[c * 68 + k], x1 = stage[(c + 1) * 68 + k];
        __half2 h = __floats2half2_rn(x0, x1);
        float2 hb = __half22float2(h);
        __half2 l = __floats2half2_rn(x0 - hb.x, x1 - hb.y);
        uint32_t off = (uint32_t)k * 128u + ((((uint32_t)c) * 2u) ^ ((((uint32_t)k) & 7u) << 4));
        *(uint32_t*)(smem + KHI + off) = u32h2(h);
        *(uint32_t*)(smem + KLO + off) = u32h2(l);
    }
    __syncthreads();   // stage (J region) reads done before J convert writes

    float D2[8][4];
    #pragma unroll
    for (int nt = 0; nt < 8; nt++)
        #pragma unroll
        for (int i = 0; i < 4; i++) D2[nt][i] = 0.0f;
    float rsum[2] = {0.0f, 0.0f};

    // lane-constant address pieces
    const uint32_t xorl  = (uint32_t)(lane & 7) << 4;
    const uint32_t aRow0 = (uint32_t)(m0 + (lane & 15)) * 128u;
    const uint32_t aColH = (uint32_t)((lane >> 4) << 4);
    const uint32_t bRowJ = (uint32_t)((lane & 15)) * 128u;
    const uint32_t bColJ = (uint32_t)((lane >> 4) << 4);
    const uint32_t vRow  = (uint32_t)(lane & 7) * 128u;
    const uint32_t vColH = (uint32_t)((lane >> 3) << 4);
    const uint32_t vcol  = ((uint32_t)(j0 * 2) + vColH) ^ xorl;

    for (int jt = 0; jt < 16; jt++) {
        // ---------- convert J (from prefetched regs) -> fp16 hi/lo smem ----------
        #pragma unroll
        for (int t = 0; t < 4; t++) {
            float4 jv = jreg[t];
            __half2 jh0 = __floats2half2_rn(jv.x, jv.y), jh1 = __floats2half2_rn(jv.z, jv.w);
            float2 f0 = __half22float2(jh0), f1 = __half22float2(jh1);
            __half2 jl0 = __floats2half2_rn(jv.x - f0.x, jv.y - f0.y);
            __half2 jl1 = __floats2half2_rn(jv.z - f1.x, jv.w - f1.y);
            *(uint2*)(smem + JHI + soffs[t]) = make_uint2(u32h2(jh0), u32h2(jh1));
            *(uint2*)(smem + JLO + soffs[t]) = make_uint2(u32h2(jl0), u32h2(jl1));
        }
        // issue V loads (in flight during GEMM1)
        float4 vreg[4];
        #pragma unroll
        for (int t = 0; t < 4; t++)
            vreg[t] = *(const float4*)(Vg + goffs[t] + (unsigned)jt * 64u);
        __syncthreads();

        // ---------- GEMM1: S[16 x 32] ----------
        float S[4][4];
        #pragma unroll
        for (int nt = 0; nt < 4; nt++)
            #pragma unroll
            for (int i = 0; i < 4; i++) S[nt][i] = 0.0f;

        #pragma unroll
        for (int ks = 0; ks < 4; ks++) {
            uint32_t ah[4], al[4];
            uint32_t acol = ((uint32_t)(ks * 32) + aColH) ^ xorl;
            ldsm4(ah, smb + KHI + aRow0 + acol);
            ldsm4(al, smb + KLO + aRow0 + acol);
            uint32_t jrow = (uint32_t)(ks * 16) * 128u + bRowJ;
            #pragma unroll
            for (int ntp = 0; ntp < 2; ntp++) {
                uint32_t bh[4], bl[4];
                uint32_t bcol = ((uint32_t)((j0 + ntp * 16) * 2) + bColJ) ^ xorl;
                ldsm4t(bh, smb + JHI + jrow + bcol);
                ldsm4t(bl, smb + JLO + jrow + bcol);
                #pragma unroll
                for (int q = 0; q < 2; q++) {
                    int nt = 2 * ntp + q;
                    mma_f16(S[nt], ah, bh[2 * q], bh[2 * q + 1]);
                    mma_f16(S[nt], ah, bl[2 * q], bl[2 * q + 1]);
                    mma_f16(S[nt], al, bh[2 * q], bh[2 * q + 1]);
                }
            }
        }

        // ---------- softmax: P = exp(S), bf16 hi/lo A-fragments (2 k-groups) ----------
        uint32_t phi[2][4], plo[2][4];
        #pragma unroll
        for (int g = 0; g < 2; g++)
            #pragma unroll
            for (int q = 0; q < 2; q++) {
                const float* s = S[2 * g + q];
                float p0 = __expf(s[0]), p1 = __expf(s[1]);
                float p2 = __expf(s[2]), p3 = __expf(s[3]);
                rsum[0] += p0 + p1;
                rsum[1] += p2 + p3;
                __nv_bfloat162 h01 = __floats2bfloat162_rn(p0, p1);
                __nv_bfloat162 h23 = __floats2bfloat162_rn(p2, p3);
                float2 b01 = __bfloat1622float2(h01), b23 = __bfloat1622float2(h23);
                __nv_bfloat162 l01 = __floats2bfloat162_rn(p0 - b01.x, p1 - b01.y);
                __nv_bfloat162 l23 = __floats2bfloat162_rn(p2 - b23.x, p3 - b23.y);
                phi[g][2 * q]     = u32b2(h01);
                phi[g][2 * q + 1] = u32b2(h23);
                plo[g][2 * q]     = u32b2(l01);
                plo[g][2 * q + 1] = u32b2(l23);
            }

        // ---------- convert V (from regs) -> bf16 hi/lo smem ----------
        #pragma unroll
        for (int t = 0; t < 4; t++) {
            float4 vv = vreg[t];
            __nv_bfloat162 vh0 = __floats2bfloat162_rn(vv.x, vv.y), vh1 = __floats2bfloat162_rn(vv.z, vv.w);
            float2 g0 = __bfloat1622float2(vh0), g1 = __bfloat1622float2(vh1);
            __nv_bfloat162 vl0 = __floats2bfloat162_rn(vv.x - g0.x, vv.y - g0.y);
            __nv_bfloat162 vl1 = __floats2bfloat162_rn(vv.z - g1.x, vv.w - g1.y);
            *(uint2*)(smem + VHI + soffs[t]) = make_uint2(u32b2(vh0), u32b2(vh1));
            *(uint2*)(smem + VLO + soffs[t]) = make_uint2(u32b2(vl0), u32b2(vl1));
        }
        __syncthreads();

        // prefetch J for next iter (in flight during GEMM2)
        if (jt < 15) {
            #pragma unroll
            for (int t = 0; t < 4; t++)
                jreg[t] = *(const float4*)(Jg + goffs[t] + (unsigned)(jt + 1) * 64u);
        }

        // ---------- GEMM2: D2 += P x V^T over this 32-j half ----------
        #pragma unroll
        for (int nt = 0; nt < 8; nt++) {
            uint32_t bh[4], bl[4];
            uint32_t vr = (uint32_t)(nt * 8) * 128u + vRow;
            ldsm4(bh, smb + VHI + vr + vcol);
            ldsm4(bl, smb + VLO + vr + vcol);
            #pragma unroll
            for (int g = 0; g < 2; g++) {
                mma_bf16(D2[nt], phi[g], bh[2 * g], bh[2 * g + 1]);
                mma_bf16(D2[nt], phi[g], bl[2 * g], bl[2 * g + 1]);
                mma_bf16(D2[nt], plo[g], bh[2 * g], bh[2 * g + 1]);
            }
        }
    }

    // ---------- Epilogue ----------
    #pragma unroll
    for (int rr = 0; rr < 2; rr++) {
        float v = rsum[rr];
        v += __shfl_xor_sync(0xffffffffu, v, 1);
        v += __shfl_xor_sync(0xffffffffu, v, 2);
        if ((lane & 3) == 0)
            lred[wn * 64 + m0 + rr * 8 + (lane >> 2)] = v;
    }
    __syncthreads();
    if (tid < 64) lred[128 + tid] = 1.0f / (lred[tid] + lred[64 + tid]);

    if (wn == 0) {
        #pragma unroll
        for (int nt = 0; nt < 8; nt++) {
            int c0 = nt * 8 + 2 * (lane & 3);
            int r = m0 + (lane >> 2);
            ostage[c0 * 64 + r]           = D2[nt][0];
            ostage[(c0 + 1) * 64 + r]     = D2[nt][1];
            ostage[c0 * 64 + r + 8]       = D2[nt][2];
            ostage[(c0 + 1) * 64 + r + 8] = D2[nt][3];
        }
    }
    __syncthreads();
    if (wn == 1) {
        #pragma unroll
        for (int nt = 0; nt < 8; nt++) {
            int c0 = nt * 8 + 2 * (lane & 3);
            int r = m0 + (lane >> 2);
            ostage[c0 * 64 + r]           += D2[nt][0];
            ostage[(c0 + 1) * 64 + r]     += D2[nt][1];
            ostage[c0 * 64 + r + 8]       += D2[nt][2];
            ostage[(c0 + 1) * 64 + r + 8] += D2[nt][3];
        }
    }
    __syncthreads();

    #pragma unroll
    for (int t = 0; t < 4; t++) {
        int c = cc[t], k4 = cj4[t];
        float4 v  = *(float4*)(ostage + c * 64 + k4 * 4);
        float4 iv = *(float4*)(lred + 128 + k4 * 4);
        v.x *= iv.x; v.y *= iv.y; v.z *= iv.z; v.w *= iv.w;
        *(float4*)(Og + base + (unsigned)c * 1024u + kbase + (unsigned)k4 * 4u) = v;
    }
}

extern "C" void kernel_launch(void* const* d_in, const int* in_sizes, int n_in,
                              void* d_out, int out_size) {
    const float* Kg = (const float*)d_in[0];
    const float* Jg = (const float*)d_in[1];
    const float* Vg = (const float*)d_in[2];
    float* Og = (float*)d_out;

    cudaFuncSetAttribute(attn_mma_kernel,
                         cudaFuncAttributeMaxDynamicSharedMemorySize, SMEM_BYTES);
    dim3 grid(16, 64);   // 16 k-tiles x 64 batches = 1024 CTAs, 2 per SM
    attn_mma_kernel<<<grid, NTHREADS, SMEM_BYTES>>>(Kg, Jg, Vg, Og);
}

// round 8
// speedup vs baseline: 1.2789x; 1.0542x over previous
#include <cuda_runtime.h>
#include <cuda_fp16.h>
#include <cuda_bf16.h>
#include <cstdint>

// self_attention_9225589752302 — round 7: pre-split J/V/K^T in global scratch,
// cp.async double-buffered mainloop, K fragments cached in registers.
// GEMM1 fp16 hi/lo 3-pass, GEMM2 bf16 hi/lo 3-pass. grid (16 k-tiles, 64 batches), 2 CTAs/SM.

#define NTHREADS 256

// ---- global scratch (48MB) ----
__device__ __half         g_KtHi[4194304];   // [pb][k=1024][c=64]
__device__ __half         g_KtLo[4194304];
__device__ __half         g_JHi [4194304];   // [pb][c=64][j=1024]
__device__ __half         g_JLo [4194304];
__device__ __nv_bfloat16  g_VHi [4194304];   // [pb][c=64][j=1024]
__device__ __nv_bfloat16  g_VLo [4194304];

// ---- smem layout ----
#define KHIo 0u            // K^T [k=64][c=64] fp16, 128B rows, swz ((k&7)<<4)
#define KLOo 8192u
#define STG  16384u        // stage 0 base; stage 1 at +32768
#define SSZ  32768u
#define JHIo 0u            // within stage: J [c=64][j=64] fp16
#define JLOo 8192u
#define VHIo 16384u        // V [c=64][j=64] bf16
#define VLOo 24576u
#define LRED 81920u        // 192 f32
#define SMEM_BYTES (81920u + 1024u)
#define OSTAGE 0u          // epilogue f32 [64][64] over K tiles

static __device__ __forceinline__ uint32_t smem_u32(const void* p) {
    uint32_t a;
    asm("{ .reg .u64 t; cvta.to.shared.u64 t, %1; cvt.u32.u64 %0, t; }" : "=r"(a) : "l"(p));
    return a;
}
static __device__ __forceinline__ void cpa16(uint32_t dst, const void* src) {
    asm volatile("cp.async.cg.shared.global [%0], [%1], 16;" :: "r"(dst), "l"(src));
}
#define CP_COMMIT() asm volatile("cp.async.commit_group;" ::: "memory")
#define CP_WAIT0()  asm volatile("cp.async.wait_group 0;" ::: "memory")

static __device__ __forceinline__ void ldsm4(uint32_t r[4], uint32_t a) {
    asm volatile("ldmatrix.sync.aligned.m8n8.x4.shared.b16 {%0,%1,%2,%3}, [%4];"
        : "=r"(r[0]), "=r"(r[1]), "=r"(r[2]), "=r"(r[3]) : "r"(a));
}
static __device__ __forceinline__ void ldsm4t(uint32_t r[4], uint32_t a) {
    asm volatile("ldmatrix.sync.aligned.m8n8.x4.trans.shared.b16 {%0,%1,%2,%3}, [%4];"
        : "=r"(r[0]), "=r"(r[1]), "=r"(r[2]), "=r"(r[3]) : "r"(a));
}
static __device__ __forceinline__ void mma_f16(float d[4], const uint32_t a[4], uint32_t b0, uint32_t b1) {
    asm("mma.sync.aligned.m16n8k16.row.col.f32.f16.f16.f32 "
        "{%0,%1,%2,%3}, {%4,%5,%6,%7}, {%8,%9}, {%0,%1,%2,%3};"
        : "+f"(d[0]), "+f"(d[1]), "+f"(d[2]), "+f"(d[3])
        : "r"(a[0]), "r"(a[1]), "r"(a[2]), "r"(a[3]), "r"(b0), "r"(b1));
}
static __device__ __forceinline__ void mma_bf16(float d[4], const uint32_t a[4], uint32_t b0, uint32_t b1) {
    asm("mma.sync.aligned.m16n8k16.row.col.f32.bf16.bf16.f32 "
        "{%0,%1,%2,%3}, {%4,%5,%6,%7}, {%8,%9}, {%0,%1,%2,%3};"
        : "+f"(d[0]), "+f"(d[1]), "+f"(d[2]), "+f"(d[3])
        : "r"(a[0]), "r"(a[1]), "r"(a[2]), "r"(a[3]), "r"(b0), "r"(b1));
}
static __device__ __forceinline__ uint32_t u32b2(__nv_bfloat162 h) { return *(uint32_t*)&h; }

// ---- prep kernel 1: elementwise split of J (fp16) and V (bf16) ----
__global__ __launch_bounds__(256)
void split_jv_kernel(const float* __restrict__ J, const float* __restrict__ V) {
    unsigned f = blockIdx.x * 256u + threadIdx.x;   // float4 index, 1048576 total
    float4 jv = ((const float4*)J)[f];
    __half2 h0 = __floats2half2_rn(jv.x, jv.y), h1 = __floats2half2_rn(jv.z, jv.w);
    float2 a0 = __half22float2(h0), a1 = __half22float2(h1);
    __half2 l0 = __floats2half2_rn(jv.x - a0.x, jv.y - a0.y);
    __half2 l1 = __floats2half2_rn(jv.z - a1.x, jv.w - a1.y);
    ((__half2*)g_JHi)[f * 2] = h0; ((__half2*)g_JHi)[f * 2 + 1] = h1;
    ((__half2*)g_JLo)[f * 2] = l0; ((__half2*)g_JLo)[f * 2 + 1] = l1;
    float4 vv = ((const float4*)V)[f];
    __nv_bfloat162 b0 = __floats2bfloat162_rn(vv.x, vv.y), b1 = __floats2bfloat162_rn(vv.z, vv.w);
    float2 c0 = __bfloat1622float2(b0), c1 = __bfloat1622float2(b1);
    __nv_bfloat162 m0 = __floats2bfloat162_rn(vv.x - c0.x, vv.y - c0.y);
    __nv_bfloat162 m1 = __floats2bfloat162_rn(vv.z - c1.x, vv.w - c1.y);
    ((__nv_bfloat162*)g_VHi)[f * 2] = b0; ((__nv_bfloat162*)g_VHi)[f * 2 + 1] = b1;
    ((__nv_bfloat162*)g_VLo)[f * 2] = m0; ((__nv_bfloat162*)g_VLo)[f * 2 + 1] = m1;
}

// ---- prep kernel 2: K^T transpose + fp16 split ----
__global__ __launch_bounds__(256)
void transpose_k_kernel(const float* __restrict__ K) {
    __shared__ float s[64][65];
    const int tid = threadIdx.x;
    const unsigned base = (unsigned)blockIdx.y * 65536u;
    const unsigned k0 = (unsigned)blockIdx.x * 64u;
    #pragma unroll
    for (int t = 0; t < 16; t++) {
        int flat = tid + t * 256;
        int c = flat >> 6, k = flat & 63;
        s[c][k] = K[base + (unsigned)c * 1024u + k0 + k];
    }
    __syncthreads();
    #pragma unroll
    for (int t = 0; t < 16; t++) {
        int flat = tid + t * 256;
        int k = flat >> 6, c = flat & 63;
        float x = s[c][k];
        __half h = __float2half_rn(x);
        __half l = __float2half_rn(x - __half2float(h));
        unsigned o = base + (k0 + (unsigned)k) * 64u + (unsigned)c;
        g_KtHi[o] = h;
        g_KtLo[o] = l;
    }
}

// ---- main kernel ----
__global__ __launch_bounds__(NTHREADS, 2)
void attn_mma_kernel(float* __restrict__ Og) {
    extern __shared__ char smem[];
    const uint32_t smb = smem_u32(smem);
    float* lred  = (float*)(smem + LRED);
    float* ostage = (float*)(smem + OSTAGE);

    const int tid  = threadIdx.x;
    const int lane = tid & 31;
    const int wid  = tid >> 5;
    const int wm   = wid & 3;      // m-strip: rows 16*wm..+15 (of 64)
    const int wn   = wid >> 2;     // j-half: 32*wn..+31 (of 64)
    const int m0   = wm * 16;
    const int j0   = wn * 32;
    const unsigned pbo   = (unsigned)blockIdx.y * 65536u;
    const unsigned kbase = (unsigned)blockIdx.x * 64u;

    // ---------- prologue: cp.async K tile + stage 0 ----------
    #pragma unroll
    for (int t = 0; t < 2; t++) {
        int flat = tid + t * NTHREADS;               // 512 chunks
        uint32_t k = (uint32_t)(flat >> 3), ch = (uint32_t)(flat & 7);
        uint32_t dst = k * 128u + ((ch * 16u) ^ ((k & 7u) << 4));
        unsigned so = pbo + (kbase + k) * 64u + ch * 8u;
        cpa16(smb + KHIo + dst, g_KtHi + so);
        cpa16(smb + KLOo + dst, g_KtLo + so);
    }
    #pragma unroll
    for (int t = 0; t < 2; t++) {
        int flat = tid + t * NTHREADS;
        uint32_t c = (uint32_t)(flat >> 3), ch = (uint32_t)(flat & 7);
        uint32_t dst = c * 128u + ((ch * 16u) ^ ((c & 7u) << 4));
        unsigned so = pbo + c * 1024u + ch * 8u;     // jt = 0
        cpa16(smb + STG + JHIo + dst, g_JHi + so);
        cpa16(smb + STG + JLOo + dst, g_JLo + so);
        cpa16(smb + STG + VHIo + dst, g_VHi + so);
        cpa16(smb + STG + VLOo + dst, g_VLo + so);
    }
    CP_COMMIT();
    CP_WAIT0();
    __syncthreads();

    // lane-constant address pieces
    const uint32_t xorl  = (uint32_t)(lane & 7) << 4;
    const uint32_t aRow0 = (uint32_t)(m0 + (lane & 15)) * 128u;
    const uint32_t aColH = (uint32_t)((lane >> 4) << 4);
    const uint32_t bRowJ = (uint32_t)((lane & 15)) * 128u;
    const uint32_t bColJ = (uint32_t)((lane >> 4) << 4);
    const uint32_t vRow  = (uint32_t)(lane & 7) * 128u;
    const uint32_t vColH = (uint32_t)((lane >> 3) << 4);
    const uint32_t vcol  = ((uint32_t)(j0 * 2) + vColH) ^ xorl;

    // ---------- cache K fragments in registers (static across all iters) ----------
    uint32_t kfh[4][4], kfl[4][4];
    #pragma unroll
    for (int ks = 0; ks < 4; ks++) {
        uint32_t acol = ((uint32_t)(ks * 32) + aColH) ^ xorl;
        ldsm4(kfh[ks], smb + KHIo + aRow0 + acol);
        ldsm4(kfl[ks], smb + KLOo + aRow0 + acol);
    }

    float D2[8][4];
    #pragma unroll
    for (int nt = 0; nt < 8; nt++)
        #pragma unroll
        for (int i = 0; i < 4; i++) D2[nt][i] = 0.0f;
    float rsum[2] = {0.0f, 0.0f};

    for (int jt = 0; jt < 16; jt++) {
        const uint32_t cur = STG + (uint32_t)(jt & 1) * SSZ;

        // ---------- issue next-stage copies (overlap with GEMMs) ----------
        if (jt < 15) {
            const uint32_t nxt = STG + (uint32_t)((jt + 1) & 1) * SSZ;
            #pragma unroll
            for (int t = 0; t < 2; t++) {
                int flat = tid + t * NTHREADS;
                uint32_t c = (uint32_t)(flat >> 3), ch = (uint32_t)(flat & 7);
                uint32_t dst = c * 128u + ((ch * 16u) ^ ((c & 7u) << 4));
                unsigned so = pbo + c * 1024u + (unsigned)(jt + 1) * 64u + ch * 8u;
                cpa16(smb + nxt + JHIo + dst, g_JHi + so);
                cpa16(smb + nxt + JLOo + dst, g_JLo + so);
                cpa16(smb + nxt + VHIo + dst, g_VHi + so);
                cpa16(smb + nxt + VLOo + dst, g_VLo + so);
            }
            CP_COMMIT();
        }

        // ---------- GEMM1: S[16 x 32] ----------
        float S[4][4];
        #pragma unroll
        for (int nt = 0; nt < 4; nt++)
            #pragma unroll
            for (int i = 0; i < 4; i++) S[nt][i] = 0.0f;

        #pragma unroll
        for (int ks = 0; ks < 4; ks++) {
            uint32_t jrow = (uint32_t)(ks * 16) * 128u + bRowJ;
            #pragma unroll
            for (int ntp = 0; ntp < 2; ntp++) {
                uint32_t bh[4], bl[4];
                uint32_t bcol = ((uint32_t)((j0 + ntp * 16) * 2) + bColJ) ^ xorl;
                ldsm4t(bh, smb + cur + JHIo + jrow + bcol);
                ldsm4t(bl, smb + cur + JLOo + jrow + bcol);
                #pragma unroll
                for (int q = 0; q < 2; q++) {
                    int nt = 2 * ntp + q;
                    mma_f16(S[nt], kfh[ks], bh[2 * q], bh[2 * q + 1]);
                    mma_f16(S[nt], kfh[ks], bl[2 * q], bl[2 * q + 1]);
                    mma_f16(S[nt], kfl[ks], bh[2 * q], bh[2 * q + 1]);
                }
            }
        }

        // ---------- softmax: P = exp(S), bf16 hi/lo A-fragments ----------
        uint32_t phi[2][4], plo[2][4];
        #pragma unroll
        for (int g = 0; g < 2; g++)
            #pragma unroll
            for (int q = 0; q < 2; q++) {
                const float* s = S[2 * g + q];
                float p0 = __expf(s[0]), p1 = __expf(s[1]);
                float p2 = __expf(s[2]), p3 = __expf(s[3]);
                rsum[0] += p0 + p1;
                rsum[1] += p2 + p3;
                __nv_bfloat162 h01 = __floats2bfloat162_rn(p0, p1);
                __nv_bfloat162 h23 = __floats2bfloat162_rn(p2, p3);
                float2 b01 = __bfloat1622float2(h01), b23 = __bfloat1622float2(h23);
                __nv_bfloat162 l01 = __floats2bfloat162_rn(p0 - b01.x, p1 - b01.y);
                __nv_bfloat162 l23 = __floats2bfloat162_rn(p2 - b23.x, p3 - b23.y);
                phi[g][2 * q]     = u32b2(h01);
                phi[g][2 * q + 1] = u32b2(h23);
                plo[g][2 * q]     = u32b2(l01);
                plo[g][2 * q + 1] = u32b2(l23);
            }

        // ---------- GEMM2: D2 += P x V^T over this 32-j half ----------
        #pragma unroll
        for (int nt = 0; nt < 8; nt++) {
            uint32_t bh[4], bl[4];
            uint32_t vr = (uint32_t)(nt * 8) * 128u + vRow;
            ldsm4(bh, smb + cur + VHIo + vr + vcol);
            ldsm4(bl, smb + cur + VLOo + vr + vcol);
            #pragma unroll
            for (int g = 0; g < 2; g++) {
                mma_bf16(D2[nt], phi[g], bh[2 * g], bh[2 * g + 1]);
                mma_bf16(D2[nt], phi[g], bl[2 * g], bl[2 * g + 1]);
                mma_bf16(D2[nt], plo[g], bh[2 * g], bh[2 * g + 1]);
            }
        }

        if (jt < 15) CP_WAIT0();
        __syncthreads();
    }

    // ---------- Epilogue ----------
    #pragma unroll
    for (int rr = 0; rr < 2; rr++) {
        float v = rsum[rr];
        v += __shfl_xor_sync(0xffffffffu, v, 1);
        v += __shfl_xor_sync(0xffffffffu, v, 2);
        if ((lane & 3) == 0)
            lred[wn * 64 + m0 + rr * 8 + (lane >> 2)] = v;
    }
    __syncthreads();
    if (tid < 64) lred[128 + tid] = 1.0f / (lred[tid] + lred[64 + tid]);

    if (wn == 0) {
        #pragma unroll
        for (int nt = 0; nt < 8; nt++) {
            int c0 = nt * 8 + 2 * (lane & 3);
            int r = m0 + (lane >> 2);
            ostage[c0 * 64 + r]           = D2[nt][0];
            ostage[(c0 + 1) * 64 + r]     = D2[nt][1];
            ostage[c0 * 64 + r + 8]       = D2[nt][2];
            ostage[(c0 + 1) * 64 + r + 8] = D2[nt][3];
        }
    }
    __syncthreads();
    if (wn == 1) {
        #pragma unroll
        for (int nt = 0; nt < 8; nt++) {
            int c0 = nt * 8 + 2 * (lane & 3);
            int r = m0 + (lane >> 2);
            ostage[c0 * 64 + r]           += D2[nt][0];
            ostage[(c0 + 1) * 64 + r]     += D2[nt][1];
            ostage[c0 * 64 + r + 8]       += D2[nt][2];
            ostage[(c0 + 1) * 64 + r + 8] += D2[nt][3];
        }
    }
    __syncthreads();

    #pragma unroll
    for (int t = 0; t < 4; t++) {
        int flat = tid + t * NTHREADS;
        int c = flat >> 4, k4 = flat & 15;
        float4 v  = *(float4*)(ostage + c * 64 + k4 * 4);
        float4 iv = *(float4*)(lred + 128 + k4 * 4);
        v.x *= iv.x; v.y *= iv.y; v.z *= iv.z; v.w *= iv.w;
        *(float4*)(Og + pbo + (unsigned)c * 1024u + kbase + (unsigned)k4 * 4u) = v;
    }
}

extern "C" void kernel_launch(void* const* d_in, const int* in_sizes, int n_in,
                              void* d_out, int out_size) {
    const float* Kg = (const float*)d_in[0];
    const float* Jg = (const float*)d_in[1];
    const float* Vg = (const float*)d_in[2];
    float* Og = (float*)d_out;

    split_jv_kernel<<<4096, 256>>>(Jg, Vg);
    transpose_k_kernel<<<dim3(16, 64), 256>>>(Kg);

    cudaFuncSetAttribute(attn_mma_kernel,
                         cudaFuncAttributeMaxDynamicSharedMemorySize, SMEM_BYTES);
    dim3 grid(16, 64);   // 16 k-tiles x 64 batches = 1024 CTAs, 2 per SM
    attn_mma_kernel<<<grid, NTHREADS, SMEM_BYTES>>>(Og);
}

// round 9
// speedup vs baseline: 1.3392x; 1.0472x over previous
#include <cuda_runtime.h>
#include <cuda_fp16.h>
#include <cuda_bf16.h>
#include <cstdint>

// self_attention_9225589752302 — round 8: online row-max -> fp16 2-pass GEMM2 (V single fp16)
// GEMM1 fp16 hi/lo 3-pass (K^T cached in regs), GEMM2 fp16 P-split 2-pass.
// grid (16 k-tiles, 64 batches), 256 thr, 2 CTAs/SM, cp.async double-buffered J/V.

#define NTHREADS 256

// ---- global scratch ----
__device__ __half g_KtHi[4194304];   // [pb][k=1024][c=64]
__device__ __half g_KtLo[4194304];
__device__ __half g_JHi [4194304];   // [pb][c=64][j=1024]
__device__ __half g_JLo [4194304];
__device__ __half g_VH  [4194304];   // [pb][c=64][j=1024] single fp16

// ---- smem layout ----
#define KHIo 0u            // K^T [k=64][c=64] fp16, 128B rows, swz ((k&7)<<4)
#define KLOo 8192u
#define STG  16384u        // stage 0; stage 1 at +24576
#define SSZ  24576u
#define JHIo 0u            // within stage: J [c=64][j=64] fp16
#define JLOo 8192u
#define VHo  16384u        // V [c=64][j=64] fp16
#define LRED 65536u        // f32: [0..127] rsum partials, [128..191] 1/l, [192..319] row maxes
#define SMEM_BYTES (65536u + 1536u)
#define OSTAGE 0u          // epilogue f32 [64][64] over K tiles

static __device__ __forceinline__ uint32_t smem_u32(const void* p) {
    uint32_t a;
    asm("{ .reg .u64 t; cvta.to.shared.u64 t, %1; cvt.u32.u64 %0, t; }" : "=r"(a) : "l"(p));
    return a;
}
static __device__ __forceinline__ void cpa16(uint32_t dst, const void* src) {
    asm volatile("cp.async.cg.shared.global [%0], [%1], 16;" :: "r"(dst), "l"(src));
}
#define CP_COMMIT() asm volatile("cp.async.commit_group;" ::: "memory")
#define CP_WAIT0()  asm volatile("cp.async.wait_group 0;" ::: "memory")

static __device__ __forceinline__ void ldsm4(uint32_t r[4], uint32_t a) {
    asm volatile("ldmatrix.sync.aligned.m8n8.x4.shared.b16 {%0,%1,%2,%3}, [%4];"
        : "=r"(r[0]), "=r"(r[1]), "=r"(r[2]), "=r"(r[3]) : "r"(a));
}
static __device__ __forceinline__ void ldsm4t(uint32_t r[4], uint32_t a) {
    asm volatile("ldmatrix.sync.aligned.m8n8.x4.trans.shared.b16 {%0,%1,%2,%3}, [%4];"
        : "=r"(r[0]), "=r"(r[1]), "=r"(r[2]), "=r"(r[3]) : "r"(a));
}
static __device__ __forceinline__ void mma_f16(float d[4], const uint32_t a[4], uint32_t b0, uint32_t b1) {
    asm("mma.sync.aligned.m16n8k16.row.col.f32.f16.f16.f32 "
        "{%0,%1,%2,%3}, {%4,%5,%6,%7}, {%8,%9}, {%0,%1,%2,%3};"
        : "+f"(d[0]), "+f"(d[1]), "+f"(d[2]), "+f"(d[3])
        : "r"(a[0]), "r"(a[1]), "r"(a[2]), "r"(a[3]), "r"(b0), "r"(b1));
}
static __device__ __forceinline__ uint32_t u32h2(__half2 h) { return *(uint32_t*)&h; }

// ---- prep 1: split J to fp16 hi/lo, round V to fp16 ----
__global__ __launch_bounds__(256)
void split_jv_kernel(const float* __restrict__ J, const float* __restrict__ V) {
    unsigned f = blockIdx.x * 256u + threadIdx.x;   // float4 index
    float4 jv = ((const float4*)J)[f];
    __half2 h0 = __floats2half2_rn(jv.x, jv.y), h1 = __floats2half2_rn(jv.z, jv.w);
    float2 a0 = __half22float2(h0), a1 = __half22float2(h1);
    __half2 l0 = __floats2half2_rn(jv.x - a0.x, jv.y - a0.y);
    __half2 l1 = __floats2half2_rn(jv.z - a1.x, jv.w - a1.y);
    ((__half2*)g_JHi)[f * 2] = h0; ((__half2*)g_JHi)[f * 2 + 1] = h1;
    ((__half2*)g_JLo)[f * 2] = l0; ((__half2*)g_JLo)[f * 2 + 1] = l1;
    float4 vv = ((const float4*)V)[f];
    ((__half2*)g_VH)[f * 2]     = __floats2half2_rn(vv.x, vv.y);
    ((__half2*)g_VH)[f * 2 + 1] = __floats2half2_rn(vv.z, vv.w);
}

// ---- prep 2: K^T transpose + fp16 split ----
__global__ __launch_bounds__(256)
void transpose_k_kernel(const float* __restrict__ K) {
    __shared__ float s[64][65];
    const int tid = threadIdx.x;
    const unsigned base = (unsigned)blockIdx.y * 65536u;
    const unsigned k0 = (unsigned)blockIdx.x * 64u;
    #pragma unroll
    for (int t = 0; t < 16; t++) {
        int flat = tid + t * 256;
        int c = flat >> 6, k = flat & 63;
        s[c][k] = K[base + (unsigned)c * 1024u + k0 + k];
    }
    __syncthreads();
    #pragma unroll
    for (int t = 0; t < 16; t++) {
        int flat = tid + t * 256;
        int k = flat >> 6, c = flat & 63;
        float x = s[c][k];
        __half h = __float2half_rn(x);
        __half l = __float2half_rn(x - __half2float(h));
        unsigned o = base + (k0 + (unsigned)k) * 64u + (unsigned)c;
        g_KtHi[o] = h;
        g_KtLo[o] = l;
    }
}

// ---- main kernel ----
__global__ __launch_bounds__(NTHREADS, 2)
void attn_mma_kernel(float* __restrict__ Og) {
    extern __shared__ char smem[];
    const uint32_t smb = smem_u32(smem);
    float* lred  = (float*)(smem + LRED);
    float* msm   = lred + 192;
    float* ostage = (float*)(smem + OSTAGE);

    const int tid  = threadIdx.x;
    const int lane = tid & 31;
    const int wid  = tid >> 5;
    const int wm   = wid & 3;      // m-strip: rows 16*wm..+15 (of 64)
    const int wn   = wid >> 2;     // j-half: 32*wn..+31 (of 64)
    const int m0   = wm * 16;
    const int j0   = wn * 32;
    const unsigned pbo   = (unsigned)blockIdx.y * 65536u;
    const unsigned kbase = (unsigned)blockIdx.x * 64u;

    // ---------- prologue: cp.async K tile + stage 0 ----------
    #pragma unroll
    for (int t = 0; t < 2; t++) {
        int flat = tid + t * NTHREADS;
        uint32_t k = (uint32_t)(flat >> 3), ch = (uint32_t)(flat & 7);
        uint32_t dst = k * 128u + ((ch * 16u) ^ ((k & 7u) << 4));
        unsigned so = pbo + (kbase + k) * 64u + ch * 8u;
        cpa16(smb + KHIo + dst, g_KtHi + so);
        cpa16(smb + KLOo + dst, g_KtLo + so);
    }
    #pragma unroll
    for (int t = 0; t < 2; t++) {
        int flat = tid + t * NTHREADS;
        uint32_t c = (uint32_t)(flat >> 3), ch = (uint32_t)(flat & 7);
        uint32_t dst = c * 128u + ((ch * 16u) ^ ((c & 7u) << 4));
        unsigned so = pbo + c * 1024u + ch * 8u;     // jt = 0
        cpa16(smb + STG + JHIo + dst, g_JHi + so);
        cpa16(smb + STG + JLOo + dst, g_JLo + so);
        cpa16(smb + STG + VHo  + dst, g_VH  + so);
    }
    CP_COMMIT();
    CP_WAIT0();
    __syncthreads();

    // lane-constant address pieces
    const uint32_t xorl  = (uint32_t)(lane & 7) << 4;
    const uint32_t aRow0 = (uint32_t)(m0 + (lane & 15)) * 128u;
    const uint32_t aColH = (uint32_t)((lane >> 4) << 4);
    const uint32_t bRowJ = (uint32_t)((lane & 15)) * 128u;
    const uint32_t bColJ = (uint32_t)((lane >> 4) << 4);
    const uint32_t vRow  = (uint32_t)(lane & 7) * 128u;
    const uint32_t vColH = (uint32_t)((lane >> 3) << 4);
    const uint32_t vcol  = ((uint32_t)(j0 * 2) + vColH) ^ xorl;

    // ---------- cache K fragments in registers ----------
    uint32_t kfh[4][4], kfl[4][4];
    #pragma unroll
    for (int ks = 0; ks < 4; ks++) {
        uint32_t acol = ((uint32_t)(ks * 32) + aColH) ^ xorl;
        ldsm4(kfh[ks], smb + KHIo + aRow0 + acol);
        ldsm4(kfl[ks], smb + KLOo + aRow0 + acol);
    }

    float D2[8][4];
    #pragma unroll
    for (int nt = 0; nt < 8; nt++)
        #pragma unroll
        for (int i = 0; i < 4; i++) D2[nt][i] = 0.0f;
    float rsum[2] = {0.0f, 0.0f};
    float mrow0 = -1e30f, mrow1 = -1e30f;

    for (int jt = 0; jt < 16; jt++) {
        const uint32_t cur = STG + (uint32_t)(jt & 1) * SSZ;

        // issue next-stage copies (overlap with GEMMs)
        if (jt < 15) {
            const uint32_t nxt = STG + (uint32_t)((jt + 1) & 1) * SSZ;
            #pragma unroll
            for (int t = 0; t < 2; t++) {
                int flat = tid + t * NTHREADS;
                uint32_t c = (uint32_t)(flat >> 3), ch = (uint32_t)(flat & 7);
                uint32_t dst = c * 128u + ((ch * 16u) ^ ((c & 7u) << 4));
                unsigned so = pbo + c * 1024u + (unsigned)(jt + 1) * 64u + ch * 8u;
                cpa16(smb + nxt + JHIo + dst, g_JHi + so);
                cpa16(smb + nxt + JLOo + dst, g_JLo + so);
                cpa16(smb + nxt + VHo  + dst, g_VH  + so);
            }
            CP_COMMIT();
        }

        // ---------- GEMM1: S[16 x 32] ----------
        float S[4][4];
        #pragma unroll
        for (int nt = 0; nt < 4; nt++)
            #pragma unroll
            for (int i = 0; i < 4; i++) S[nt][i] = 0.0f;

        #pragma unroll
        for (int ks = 0; ks < 4; ks++) {
            uint32_t jrow = (uint32_t)(ks * 16) * 128u + bRowJ;
            #pragma unroll
            for (int ntp = 0; ntp < 2; ntp++) {
                uint32_t bh[4], bl[4];
                uint32_t bcol = ((uint32_t)((j0 + ntp * 16) * 2) + bColJ) ^ xorl;
                ldsm4t(bh, smb + cur + JHIo + jrow + bcol);
                ldsm4t(bl, smb + cur + JLOo + jrow + bcol);
                #pragma unroll
                for (int q = 0; q < 2; q++) {
                    int nt = 2 * ntp + q;
                    mma_f16(S[nt], kfh[ks], bh[2 * q], bh[2 * q + 1]);
                    mma_f16(S[nt], kfh[ks], bl[2 * q], bl[2 * q + 1]);
                    mma_f16(S[nt], kfl[ks], bh[2 * q], bh[2 * q + 1]);
                }
            }
        }

        // ---------- online softmax: row max, rescale, P = exp(S - m) fp16 hi/lo ----------
        float mx0 = -1e30f, mx1 = -1e30f;
        #pragma unroll
        for (int nt = 0; nt < 4; nt++) {
            mx0 = fmaxf(mx0, fmaxf(S[nt][0], S[nt][1]));
            mx1 = fmaxf(mx1, fmaxf(S[nt][2], S[nt][3]));
        }
        mx0 = fmaxf(mx0, __shfl_xor_sync(0xffffffffu, mx0, 1));
        mx0 = fmaxf(mx0, __shfl_xor_sync(0xffffffffu, mx0, 2));
        mx1 = fmaxf(mx1, __shfl_xor_sync(0xffffffffu, mx1, 1));
        mx1 = fmaxf(mx1, __shfl_xor_sync(0xffffffffu, mx1, 2));
        float nm0 = fmaxf(mrow0, mx0), nm1 = fmaxf(mrow1, mx1);
        float a0 = __expf(mrow0 - nm0), a1 = __expf(mrow1 - nm1);
        mrow0 = nm0; mrow1 = nm1;
        rsum[0] *= a0; rsum[1] *= a1;
        #pragma unroll
        for (int nt = 0; nt < 8; nt++) {
            D2[nt][0] *= a0; D2[nt][1] *= a0;
            D2[nt][2] *= a1; D2[nt][3] *= a1;
        }

        uint32_t phi[2][4], plo[2][4];
        #pragma unroll
        for (int g = 0; g < 2; g++)
            #pragma unroll
            for (int q = 0; q < 2; q++) {
                const float* s = S[2 * g + q];
                float p0 = __expf(s[0] - nm0), p1 = __expf(s[1] - nm0);
                float p2 = __expf(s[2] - nm1), p3 = __expf(s[3] - nm1);
                rsum[0] += p0 + p1;
                rsum[1] += p2 + p3;
                __half2 h01 = __floats2half2_rn(p0, p1);
                __half2 h23 = __floats2half2_rn(p2, p3);
                float2 b01 = __half22float2(h01), b23 = __half22float2(h23);
                __half2 l01 = __floats2half2_rn(p0 - b01.x, p1 - b01.y);
                __half2 l23 = __floats2half2_rn(p2 - b23.x, p3 - b23.y);
                phi[g][2 * q]     = u32h2(h01);
                phi[g][2 * q + 1] = u32h2(h23);
                plo[g][2 * q]     = u32h2(l01);
                plo[g][2 * q + 1] = u32h2(l23);
            }

        // ---------- GEMM2: D2 += P x V^T, fp16, V single ----------
        #pragma unroll
        for (int nt = 0; nt < 8; nt++) {
            uint32_t vh[4];
            uint32_t vr = (uint32_t)(nt * 8) * 128u + vRow;
            ldsm4(vh, smb + cur + VHo + vr + vcol);
            #pragma unroll
            for (int g = 0; g < 2; g++) {
                mma_f16(D2[nt], phi[g], vh[2 * g], vh[2 * g + 1]);
                mma_f16(D2[nt], plo[g], vh[2 * g], vh[2 * g + 1]);
            }
        }

        if (jt < 15) CP_WAIT0();
        __syncthreads();
    }

    // ---------- Epilogue: reconcile maxes across the two j-half warps ----------
    const int r = m0 + (lane >> 2);
    if ((lane & 3) == 0) {
        msm[wn * 64 + r]     = mrow0;
        msm[wn * 64 + r + 8] = mrow1;
    }
    __syncthreads();
    {
        float M0 = fmaxf(msm[r], msm[64 + r]);
        float M1 = fmaxf(msm[r + 8], msm[64 + r + 8]);
        float s0 = __expf(mrow0 - M0), s1 = __expf(mrow1 - M1);
        rsum[0] *= s0; rsum[1] *= s1;
        #pragma unroll
        for (int nt = 0; nt < 8; nt++) {
            D2[nt][0] *= s0; D2[nt][1] *= s0;
            D2[nt][2] *= s1; D2[nt][3] *= s1;
        }
    }

    #pragma unroll
    for (int rr = 0; rr < 2; rr++) {
        float v = rsum[rr];
        v += __shfl_xor_sync(0xffffffffu, v, 1);
        v += __shfl_xor_sync(0xffffffffu, v, 2);
        if ((lane & 3) == 0)
            lred[wn * 64 + m0 + rr * 8 + (lane >> 2)] = v;
    }
    __syncthreads();
    if (tid < 64) lred[128 + tid] = 1.0f / (lred[tid] + lred[64 + tid]);

    if (wn == 0) {
        #pragma unroll
        for (int nt = 0; nt < 8; nt++) {
            int c0 = nt * 8 + 2 * (lane & 3);
            int rw = m0 + (lane >> 2);
            ostage[c0 * 64 + rw]           = D2[nt][0];
            ostage[(c0 + 1) * 64 + rw]     = D2[nt][1];
            ostage[c0 * 64 + rw + 8]       = D2[nt][2];
            ostage[(c0 + 1) * 64 + rw + 8] = D2[nt][3];
        }
    }
    __syncthreads();
    if (wn == 1) {
        #pragma unroll
        for (int nt = 0; nt < 8; nt++) {
            int c0 = nt * 8 + 2 * (lane & 3);
            int rw = m0 + (lane >> 2);
            ostage[c0 * 64 + rw]           += D2[nt][0];
            ostage[(c0 + 1) * 64 + rw]     += D2[nt][1];
            ostage[c0 * 64 + rw + 8]       += D2[nt][2];
            ostage[(c0 + 1) * 64 + rw + 8] += D2[nt][3];
        }
    }
    __syncthreads();

    #pragma unroll
    for (int t = 0; t < 4; t++) {
        int flat = tid + t * NTHREADS;
        int c = flat >> 4, k4 = flat & 15;
        float4 v  = *(float4*)(ostage + c * 64 + k4 * 4);
        float4 iv = *(float4*)(lred + 128 + k4 * 4);
        v.x *= iv.x; v.y *= iv.y; v.z *= iv.z; v.w *= iv.w;
        *(float4*)(Og + pbo + (unsigned)c * 1024u + kbase + (unsigned)k4 * 4u) = v;
    }
}

extern "C" void kernel_launch(void* const* d_in, const int* in_sizes, int n_in,
                              void* d_out, int out_size) {
    const float* Kg = (const float*)d_in[0];
    const float* Jg = (const float*)d_in[1];
    const float* Vg = (const float*)d_in[2];
    float* Og = (float*)d_out;

    split_jv_kernel<<<4096, 256>>>(Jg, Vg);
    transpose_k_kernel<<<dim3(16, 64), 256>>>(Kg);

    cudaFuncSetAttribute(attn_mma_kernel,
                         cudaFuncAttributeMaxDynamicSharedMemorySize, SMEM_BYTES);
    dim3 grid(16, 64);
    attn_mma_kernel<<<grid, NTHREADS, SMEM_BYTES>>>(Og);
}

// round 10
// speedup vs baseline: 1.6489x; 1.2313x over previous
#include <cuda_runtime.h>
#include <cuda_fp16.h>
#include <cuda_bf16.h>
#include <cstdint>

// self_attention_9225589752302 — round 9: single-fp16 P -> 1-pass GEMM2; merged prep
// GEMM1 fp16 hi/lo 3-pass (K^T cached in regs), GEMM2 fp16 1-pass (P,V single fp16).
// grid (16 k-tiles, 64 batches), 256 thr, 2 CTAs/SM, cp.async double-buffered J/V.

#define NTHREADS 256

// ---- global scratch ----
__device__ __half g_KtHi[4194304];   // [pb][k=1024][c=64]
__device__ __half g_KtLo[4194304];
__device__ __half g_JHi [4194304];   // [pb][c=64][j=1024]
__device__ __half g_JLo [4194304];
__device__ __half g_VH  [4194304];   // [pb][c=64][j=1024] single fp16

// ---- smem layout ----
#define KHIo 0u            // K^T [k=64][c=64] fp16, 128B rows, swz ((k&7)<<4)
#define KLOo 8192u
#define STG  16384u        // stage 0; stage 1 at +24576
#define SSZ  24576u
#define JHIo 0u            // within stage: J [c=64][j=64] fp16
#define JLOo 8192u
#define VHo  16384u        // V [c=64][j=64] fp16
#define LRED 65536u        // f32: [0..127] rsum partials, [128..191] 1/l, [192..319] row maxes
#define SMEM_BYTES (65536u + 1536u)
#define OSTAGE 0u          // epilogue f32 [64][64] over K tiles

static __device__ __forceinline__ uint32_t smem_u32(const void* p) {
    uint32_t a;
    asm("{ .reg .u64 t; cvta.to.shared.u64 t, %1; cvt.u32.u64 %0, t; }" : "=r"(a) : "l"(p));
    return a;
}
static __device__ __forceinline__ void cpa16(uint32_t dst, const void* src) {
    asm volatile("cp.async.cg.shared.global [%0], [%1], 16;" :: "r"(dst), "l"(src));
}
#define CP_COMMIT() asm volatile("cp.async.commit_group;" ::: "memory")
#define CP_WAIT0()  asm volatile("cp.async.wait_group 0;" ::: "memory")

static __device__ __forceinline__ void ldsm4(uint32_t r[4], uint32_t a) {
    asm volatile("ldmatrix.sync.aligned.m8n8.x4.shared.b16 {%0,%1,%2,%3}, [%4];"
        : "=r"(r[0]), "=r"(r[1]), "=r"(r[2]), "=r"(r[3]) : "r"(a));
}
static __device__ __forceinline__ void ldsm4t(uint32_t r[4], uint32_t a) {
    asm volatile("ldmatrix.sync.aligned.m8n8.x4.trans.shared.b16 {%0,%1,%2,%3}, [%4];"
        : "=r"(r[0]), "=r"(r[1]), "=r"(r[2]), "=r"(r[3]) : "r"(a));
}
static __device__ __forceinline__ void mma_f16(float d[4], const uint32_t a[4], uint32_t b0, uint32_t b1) {
    asm("mma.sync.aligned.m16n8k16.row.col.f32.f16.f16.f32 "
        "{%0,%1,%2,%3}, {%4,%5,%6,%7}, {%8,%9}, {%0,%1,%2,%3};"
        : "+f"(d[0]), "+f"(d[1]), "+f"(d[2]), "+f"(d[3])
        : "r"(a[0]), "r"(a[1]), "r"(a[2]), "r"(a[3]), "r"(b0), "r"(b1));
}
static __device__ __forceinline__ uint32_t u32h2(__half2 h) { return *(uint32_t*)&h; }

// ---- merged prep: blocks [0,4096) split J/V; blocks [4096,5120) transpose+split K ----
__global__ __launch_bounds__(256)
void prep_kernel(const float* __restrict__ K, const float* __restrict__ J,
                 const float* __restrict__ V) {
    __shared__ float s[64][65];
    const int tid = threadIdx.x;
    const unsigned b = blockIdx.x;
    if (b < 4096u) {
        unsigned f = b * 256u + tid;   // float4 index
        float4 jv = ((const float4*)J)[f];
        __half2 h0 = __floats2half2_rn(jv.x, jv.y), h1 = __floats2half2_rn(jv.z, jv.w);
        float2 a0 = __half22float2(h0), a1 = __half22float2(h1);
        __half2 l0 = __floats2half2_rn(jv.x - a0.x, jv.y - a0.y);
        __half2 l1 = __floats2half2_rn(jv.z - a1.x, jv.w - a1.y);
        ((__half2*)g_JHi)[f * 2] = h0; ((__half2*)g_JHi)[f * 2 + 1] = h1;
        ((__half2*)g_JLo)[f * 2] = l0; ((__half2*)g_JLo)[f * 2 + 1] = l1;
        float4 vv = ((const float4*)V)[f];
        ((__half2*)g_VH)[f * 2]     = __floats2half2_rn(vv.x, vv.y);
        ((__half2*)g_VH)[f * 2 + 1] = __floats2half2_rn(vv.z, vv.w);
    } else {
        const unsigned bb = b - 4096u;
        const unsigned base = (bb >> 4) * 65536u;
        const unsigned k0 = (bb & 15u) * 64u;
        #pragma unroll
        for (int t = 0; t < 16; t++) {
            int flat = tid + t * 256;
            int c = flat >> 6, k = flat & 63;
            s[c][k] = K[base + (unsigned)c * 1024u + k0 + k];
        }
        __syncthreads();
        #pragma unroll
        for (int t = 0; t < 16; t++) {
            int flat = tid + t * 256;
            int k = flat >> 6, c = flat & 63;
            float x = s[c][k];
            __half h = __float2half_rn(x);
            __half l = __float2half_rn(x - __half2float(h));
            unsigned o = base + (k0 + (unsigned)k) * 64u + (unsigned)c;
            g_KtHi[o] = h;
            g_KtLo[o] = l;
        }
    }
}

// ---- main kernel ----
__global__ __launch_bounds__(NTHREADS, 2)
void attn_mma_kernel(float* __restrict__ Og) {
    extern __shared__ char smem[];
    const uint32_t smb = smem_u32(smem);
    float* lred  = (float*)(smem + LRED);
    float* msm   = lred + 192;
    float* ostage = (float*)(smem + OSTAGE);

    const int tid  = threadIdx.x;
    const int lane = tid & 31;
    const int wid  = tid >> 5;
    const int wm   = wid & 3;      // m-strip: rows 16*wm..+15 (of 64)
    const int wn   = wid >> 2;     // j-half: 32*wn..+31 (of 64)
    const int m0   = wm * 16;
    const int j0   = wn * 32;
    const unsigned pbo   = (unsigned)blockIdx.y * 65536u;
    const unsigned kbase = (unsigned)blockIdx.x * 64u;

    // ---------- prologue: cp.async K tile + stage 0 ----------
    #pragma unroll
    for (int t = 0; t < 2; t++) {
        int flat = tid + t * NTHREADS;
        uint32_t k = (uint32_t)(flat >> 3), ch = (uint32_t)(flat & 7);
        uint32_t dst = k * 128u + ((ch * 16u) ^ ((k & 7u) << 4));
        unsigned so = pbo + (kbase + k) * 64u + ch * 8u;
        cpa16(smb + KHIo + dst, g_KtHi + so);
        cpa16(smb + KLOo + dst, g_KtLo + so);
    }
    #pragma unroll
    for (int t = 0; t < 2; t++) {
        int flat = tid + t * NTHREADS;
        uint32_t c = (uint32_t)(flat >> 3), ch = (uint32_t)(flat & 7);
        uint32_t dst = c * 128u + ((ch * 16u) ^ ((c & 7u) << 4));
        unsigned so = pbo + c * 1024u + ch * 8u;     // jt = 0
        cpa16(smb + STG + JHIo + dst, g_JHi + so);
        cpa16(smb + STG + JLOo + dst, g_JLo + so);
        cpa16(smb + STG + VHo  + dst, g_VH  + so);
    }
    CP_COMMIT();
    CP_WAIT0();
    __syncthreads();

    // lane-constant address pieces
    const uint32_t xorl  = (uint32_t)(lane & 7) << 4;
    const uint32_t aRow0 = (uint32_t)(m0 + (lane & 15)) * 128u;
    const uint32_t aColH = (uint32_t)((lane >> 4) << 4);
    const uint32_t bRowJ = (uint32_t)((lane & 15)) * 128u;
    const uint32_t bColJ = (uint32_t)((lane >> 4) << 4);
    const uint32_t vRow  = (uint32_t)(lane & 7) * 128u;
    const uint32_t vColH = (uint32_t)((lane >> 3) << 4);
    const uint32_t vcol  = ((uint32_t)(j0 * 2) + vColH) ^ xorl;

    // ---------- cache K fragments in registers ----------
    uint32_t kfh[4][4], kfl[4][4];
    #pragma unroll
    for (int ks = 0; ks < 4; ks++) {
        uint32_t acol = ((uint32_t)(ks * 32) + aColH) ^ xorl;
        ldsm4(kfh[ks], smb + KHIo + aRow0 + acol);
        ldsm4(kfl[ks], smb + KLOo + aRow0 + acol);
    }

    float D2[8][4];
    #pragma unroll
    for (int nt = 0; nt < 8; nt++)
        #pragma unroll
        for (int i = 0; i < 4; i++) D2[nt][i] = 0.0f;
    float rsum[2] = {0.0f, 0.0f};
    float mrow0 = -1e30f, mrow1 = -1e30f;

    for (int jt = 0; jt < 16; jt++) {
        const uint32_t cur = STG + (uint32_t)(jt & 1) * SSZ;

        // issue next-stage copies (overlap with GEMMs)
        if (jt < 15) {
            const uint32_t nxt = STG + (uint32_t)((jt + 1) & 1) * SSZ;
            #pragma unroll
            for (int t = 0; t < 2; t++) {
                int flat = tid + t * NTHREADS;
                uint32_t c = (uint32_t)(flat >> 3), ch = (uint32_t)(flat & 7);
                uint32_t dst = c * 128u + ((ch * 16u) ^ ((c & 7u) << 4));
                unsigned so = pbo + c * 1024u + (unsigned)(jt + 1) * 64u + ch * 8u;
                cpa16(smb + nxt + JHIo + dst, g_JHi + so);
                cpa16(smb + nxt + JLOo + dst, g_JLo + so);
                cpa16(smb + nxt + VHo  + dst, g_VH  + so);
            }
            CP_COMMIT();
        }

        // ---------- GEMM1: S[16 x 32] fp16 3-pass ----------
        float S[4][4];
        #pragma unroll
        for (int nt = 0; nt < 4; nt++)
            #pragma unroll
            for (int i = 0; i < 4; i++) S[nt][i] = 0.0f;

        #pragma unroll
        for (int ks = 0; ks < 4; ks++) {
            uint32_t jrow = (uint32_t)(ks * 16) * 128u + bRowJ;
            #pragma unroll
            for (int ntp = 0; ntp < 2; ntp++) {
                uint32_t bh[4], bl[4];
                uint32_t bcol = ((uint32_t)((j0 + ntp * 16) * 2) + bColJ) ^ xorl;
                ldsm4t(bh, smb + cur + JHIo + jrow + bcol);
                ldsm4t(bl, smb + cur + JLOo + jrow + bcol);
                #pragma unroll
                for (int q = 0; q < 2; q++) {
                    int nt = 2 * ntp + q;
                    mma_f16(S[nt], kfh[ks], bh[2 * q], bh[2 * q + 1]);
                    mma_f16(S[nt], kfh[ks], bl[2 * q], bl[2 * q + 1]);
                    mma_f16(S[nt], kfl[ks], bh[2 * q], bh[2 * q + 1]);
                }
            }
        }

        // ---------- online softmax: row max, rescale, P = exp(S - m) single fp16 ----------
        float mx0 = -1e30f, mx1 = -1e30f;
        #pragma unroll
        for (int nt = 0; nt < 4; nt++) {
            mx0 = fmaxf(mx0, fmaxf(S[nt][0], S[nt][1]));
            mx1 = fmaxf(mx1, fmaxf(S[nt][2], S[nt][3]));
        }
        mx0 = fmaxf(mx0, __shfl_xor_sync(0xffffffffu, mx0, 1));
        mx0 = fmaxf(mx0, __shfl_xor_sync(0xffffffffu, mx0, 2));
        mx1 = fmaxf(mx1, __shfl_xor_sync(0xffffffffu, mx1, 1));
        mx1 = fmaxf(mx1, __shfl_xor_sync(0xffffffffu, mx1, 2));
        float nm0 = fmaxf(mrow0, mx0), nm1 = fmaxf(mrow1, mx1);
        float a0 = __expf(mrow0 - nm0), a1 = __expf(mrow1 - nm1);
        mrow0 = nm0; mrow1 = nm1;
        rsum[0] *= a0; rsum[1] *= a1;
        #pragma unroll
        for (int nt = 0; nt < 8; nt++) {
            D2[nt][0] *= a0; D2[nt][1] *= a0;
            D2[nt][2] *= a1; D2[nt][3] *= a1;
        }

        uint32_t phi[2][4];
        #pragma unroll
        for (int g = 0; g < 2; g++)
            #pragma unroll
            for (int q = 0; q < 2; q++) {
                const float* s = S[2 * g + q];
                float p0 = __expf(s[0] - nm0), p1 = __expf(s[1] - nm0);
                float p2 = __expf(s[2] - nm1), p3 = __expf(s[3] - nm1);
                rsum[0] += p0 + p1;
                rsum[1] += p2 + p3;
                phi[g][2 * q]     = u32h2(__floats2half2_rn(p0, p1));
                phi[g][2 * q + 1] = u32h2(__floats2half2_rn(p2, p3));
            }

        // ---------- GEMM2: D2 += P x V^T, fp16 1-pass ----------
        #pragma unroll
        for (int nt = 0; nt < 8; nt++) {
            uint32_t vh[4];
            uint32_t vr = (uint32_t)(nt * 8) * 128u + vRow;
            ldsm4(vh, smb + cur + VHo + vr + vcol);
            #pragma unroll
            for (int g = 0; g < 2; g++)
                mma_f16(D2[nt], phi[g], vh[2 * g], vh[2 * g + 1]);
        }

        if (jt < 15) CP_WAIT0();
        __syncthreads();
    }

    // ---------- Epilogue: reconcile maxes across the two j-half warps ----------
    const int r = m0 + (lane >> 2);
    if ((lane & 3) == 0) {
        msm[wn * 64 + r]     = mrow0;
        msm[wn * 64 + r + 8] = mrow1;
    }
    __syncthreads();
    {
        float M0 = fmaxf(msm[r], msm[64 + r]);
        float M1 = fmaxf(msm[r + 8], msm[64 + r + 8]);
        float s0 = __expf(mrow0 - M0), s1 = __expf(mrow1 - M1);
        rsum[0] *= s0; rsum[1] *= s1;
        #pragma unroll
        for (int nt = 0; nt < 8; nt++) {
            D2[nt][0] *= s0; D2[nt][1] *= s0;
            D2[nt][2] *= s1; D2[nt][3] *= s1;
        }
    }

    #pragma unroll
    for (int rr = 0; rr < 2; rr++) {
        float v = rsum[rr];
        v += __shfl_xor_sync(0xffffffffu, v, 1);
        v += __shfl_xor_sync(0xffffffffu, v, 2);
        if ((lane & 3) == 0)
            lred[wn * 64 + m0 + rr * 8 + (lane >> 2)] = v;
    }
    __syncthreads();
    if (tid < 64) lred[128 + tid] = 1.0f / (lred[tid] + lred[64 + tid]);

    if (wn == 0) {
        #pragma unroll
        for (int nt = 0; nt < 8; nt++) {
            int c0 = nt * 8 + 2 * (lane & 3);
            int rw = m0 + (lane >> 2);
            ostage[c0 * 64 + rw]           = D2[nt][0];
            ostage[(c0 + 1) * 64 + rw]     = D2[nt][1];
            ostage[c0 * 64 + rw + 8]       = D2[nt][2];
            ostage[(c0 + 1) * 64 + rw + 8] = D2[nt][3];
        }
    }
    __syncthreads();
    if (wn == 1) {
        #pragma unroll
        for (int nt = 0; nt < 8; nt++) {
            int c0 = nt * 8 + 2 * (lane & 3);
            int rw = m0 + (lane >> 2);
            ostage[c0 * 64 + rw]           += D2[nt][0];
            ostage[(c0 + 1) * 64 + rw]     += D2[nt][1];
            ostage[c0 * 64 + rw + 8]       += D2[nt][2];
            ostage[(c0 + 1) * 64 + rw + 8] += D2[nt][3];
        }
    }
    __syncthreads();

    #pragma unroll
    for (int t = 0; t < 4; t++) {
        int flat = tid + t * NTHREADS;
        int c = flat >> 4, k4 = flat & 15;
        float4 v  = *(float4*)(ostage + c * 64 + k4 * 4);
        float4 iv = *(float4*)(lred + 128 + k4 * 4);
        v.x *= iv.x; v.y *= iv.y; v.z *= iv.z; v.w *= iv.w;
        *(float4*)(Og + pbo + (unsigned)c * 1024u + kbase + (unsigned)k4 * 4u) = v;
    }
}

extern "C" void kernel_launch(void* const* d_in, const int* in_sizes, int n_in,
                              void* d_out, int out_size) {
    const float* Kg = (const float*)d_in[0];
    const float* Jg = (const float*)d_in[1];
    const float* Vg = (const float*)d_in[2];
    float* Og = (float*)d_out;

    prep_kernel<<<5120, 256>>>(Kg, Jg, Vg);

    cudaFuncSetAttribute(attn_mma_kernel,
                         cudaFuncAttributeMaxDynamicSharedMemorySize, SMEM_BYTES);
    dim3 grid(16, 64);
    attn_mma_kernel<<<grid, NTHREADS, SMEM_BYTES>>>(Og);
}

// round 11
// speedup vs baseline: 1.7055x; 1.0343x over previous
#include <cuda_runtime.h>
#include <cuda_fp16.h>
#include <cuda_bf16.h>
#include <cstdint>

// self_attention_9225589752302 — round 10: log2-domain softmax (K pre-scaled by log2e),
// ex2.approx, warp-voted conditional D2 rescale.
// GEMM1 fp16 hi/lo 3-pass (K^T cached in regs), GEMM2 fp16 1-pass.
// grid (16 k-tiles, 64 batches), 256 thr, 2 CTAs/SM, cp.async double-buffered J/V.

#define NTHREADS 256
#define LOG2E 1.4426950408889634f

// ---- global scratch ----
__device__ __half g_KtHi[4194304];   // [pb][k=1024][c=64], pre-scaled by log2e
__device__ __half g_KtLo[4194304];
__device__ __half g_JHi [4194304];   // [pb][c=64][j=1024]
__device__ __half g_JLo [4194304];
__device__ __half g_VH  [4194304];   // [pb][c=64][j=1024] single fp16

// ---- smem layout ----
#define KHIo 0u
#define KLOo 8192u
#define STG  16384u
#define SSZ  24576u
#define JHIo 0u
#define JLOo 8192u
#define VHo  16384u
#define LRED 65536u
#define SMEM_BYTES (65536u + 1536u)
#define OSTAGE 0u

static __device__ __forceinline__ uint32_t smem_u32(const void* p) {
    uint32_t a;
    asm("{ .reg .u64 t; cvta.to.shared.u64 t, %1; cvt.u32.u64 %0, t; }" : "=r"(a) : "l"(p));
    return a;
}
static __device__ __forceinline__ float ex2f(float x) {
    float r;
    asm("ex2.approx.ftz.f32 %0, %1;" : "=f"(r) : "f"(x));
    return r;
}
static __device__ __forceinline__ void cpa16(uint32_t dst, const void* src) {
    asm volatile("cp.async.cg.shared.global [%0], [%1], 16;" :: "r"(dst), "l"(src));
}
#define CP_COMMIT() asm volatile("cp.async.commit_group;" ::: "memory")
#define CP_WAIT0()  asm volatile("cp.async.wait_group 0;" ::: "memory")

static __device__ __forceinline__ void ldsm4(uint32_t r[4], uint32_t a) {
    asm volatile("ldmatrix.sync.aligned.m8n8.x4.shared.b16 {%0,%1,%2,%3}, [%4];"
        : "=r"(r[0]), "=r"(r[1]), "=r"(r[2]), "=r"(r[3]) : "r"(a));
}
static __device__ __forceinline__ void ldsm4t(uint32_t r[4], uint32_t a) {
    asm volatile("ldmatrix.sync.aligned.m8n8.x4.trans.shared.b16 {%0,%1,%2,%3}, [%4];"
        : "=r"(r[0]), "=r"(r[1]), "=r"(r[2]), "=r"(r[3]) : "r"(a));
}
static __device__ __forceinline__ void mma_f16(float d[4], const uint32_t a[4], uint32_t b0, uint32_t b1) {
    asm("mma.sync.aligned.m16n8k16.row.col.f32.f16.f16.f32 "
        "{%0,%1,%2,%3}, {%4,%5,%6,%7}, {%8,%9}, {%0,%1,%2,%3};"
        : "+f"(d[0]), "+f"(d[1]), "+f"(d[2]), "+f"(d[3])
        : "r"(a[0]), "r"(a[1]), "r"(a[2]), "r"(a[3]), "r"(b0), "r"(b1));
}
static __device__ __forceinline__ uint32_t u32h2(__half2 h) { return *(uint32_t*)&h; }

// ---- merged prep: blocks [0,4096) split J/V; blocks [4096,5120) transpose+split K*log2e ----
__global__ __launch_bounds__(256)
void prep_kernel(const float* __restrict__ K, const float* __restrict__ J,
                 const float* __restrict__ V) {
    __shared__ float s[64][65];
    const int tid = threadIdx.x;
    const unsigned b = blockIdx.x;
    if (b < 4096u) {
        unsigned f = b * 256u + tid;
        float4 jv = ((const float4*)J)[f];
        __half2 h0 = __floats2half2_rn(jv.x, jv.y), h1 = __floats2half2_rn(jv.z, jv.w);
        float2 a0 = __half22float2(h0), a1 = __half22float2(h1);
        __half2 l0 = __floats2half2_rn(jv.x - a0.x, jv.y - a0.y);
        __half2 l1 = __floats2half2_rn(jv.z - a1.x, jv.w - a1.y);
        ((__half2*)g_JHi)[f * 2] = h0; ((__half2*)g_JHi)[f * 2 + 1] = h1;
        ((__half2*)g_JLo)[f * 2] = l0; ((__half2*)g_JLo)[f * 2 + 1] = l1;
        float4 vv = ((const float4*)V)[f];
        ((__half2*)g_VH)[f * 2]     = __floats2half2_rn(vv.x, vv.y);
        ((__half2*)g_VH)[f * 2 + 1] = __floats2half2_rn(vv.z, vv.w);
    } else {
        const unsigned bb = b - 4096u;
        const unsigned base = (bb >> 4) * 65536u;
        const unsigned k0 = (bb & 15u) * 64u;
        #pragma unroll
        for (int t = 0; t < 16; t++) {
            int flat = tid + t * 256;
            int c = flat >> 6, k = flat & 63;
            s[c][k] = K[base + (unsigned)c * 1024u + k0 + k] * LOG2E;
        }
        __syncthreads();
        #pragma unroll
        for (int t = 0; t < 16; t++) {
            int flat = tid + t * 256;
            int k = flat >> 6, c = flat & 63;
            float x = s[c][k];
            __half h = __float2half_rn(x);
            __half l = __float2half_rn(x - __half2float(h));
            unsigned o = base + (k0 + (unsigned)k) * 64u + (unsigned)c;
            g_KtHi[o] = h;
            g_KtLo[o] = l;
        }
    }
}

// ---- main kernel ----
__global__ __launch_bounds__(NTHREADS, 2)
void attn_mma_kernel(float* __restrict__ Og) {
    extern __shared__ char smem[];
    const uint32_t smb = smem_u32(smem);
    float* lred  = (float*)(smem + LRED);
    float* msm   = lred + 192;
    float* ostage = (float*)(smem + OSTAGE);

    const int tid  = threadIdx.x;
    const int lane = tid & 31;
    const int wid  = tid >> 5;
    const int wm   = wid & 3;
    const int wn   = wid >> 2;
    const int m0   = wm * 16;
    const int j0   = wn * 32;
    const unsigned pbo   = (unsigned)blockIdx.y * 65536u;
    const unsigned kbase = (unsigned)blockIdx.x * 64u;

    // ---------- prologue: cp.async K tile + stage 0 ----------
    #pragma unroll
    for (int t = 0; t < 2; t++) {
        int flat = tid + t * NTHREADS;
        uint32_t k = (uint32_t)(flat >> 3), ch = (uint32_t)(flat & 7);
        uint32_t dst = k * 128u + ((ch * 16u) ^ ((k & 7u) << 4));
        unsigned so = pbo + (kbase + k) * 64u + ch * 8u;
        cpa16(smb + KHIo + dst, g_KtHi + so);
        cpa16(smb + KLOo + dst, g_KtLo + so);
    }
    #pragma unroll
    for (int t = 0; t < 2; t++) {
        int flat = tid + t * NTHREADS;
        uint32_t c = (uint32_t)(flat >> 3), ch = (uint32_t)(flat & 7);
        uint32_t dst = c * 128u + ((ch * 16u) ^ ((c & 7u) << 4));
        unsigned so = pbo + c * 1024u + ch * 8u;
        cpa16(smb + STG + JHIo + dst, g_JHi + so);
        cpa16(smb + STG + JLOo + dst, g_JLo + so);
        cpa16(smb + STG + VHo  + dst, g_VH  + so);
    }
    CP_COMMIT();
    CP_WAIT0();
    __syncthreads();

    // lane-constant address pieces
    const uint32_t xorl  = (uint32_t)(lane & 7) << 4;
    const uint32_t aRow0 = (uint32_t)(m0 + (lane & 15)) * 128u;
    const uint32_t aColH = (uint32_t)((lane >> 4) << 4);
    const uint32_t bRowJ = (uint32_t)((lane & 15)) * 128u;
    const uint32_t bColJ = (uint32_t)((lane >> 4) << 4);
    const uint32_t vRow  = (uint32_t)(lane & 7) * 128u;
    const uint32_t vColH = (uint32_t)((lane >> 3) << 4);
    const uint32_t vcol  = ((uint32_t)(j0 * 2) + vColH) ^ xorl;

    // ---------- cache K fragments in registers ----------
    uint32_t kfh[4][4], kfl[4][4];
    #pragma unroll
    for (int ks = 0; ks < 4; ks++) {
        uint32_t acol = ((uint32_t)(ks * 32) + aColH) ^ xorl;
        ldsm4(kfh[ks], smb + KHIo + aRow0 + acol);
        ldsm4(kfl[ks], smb + KLOo + aRow0 + acol);
    }

    float D2[8][4];
    #pragma unroll
    for (int nt = 0; nt < 8; nt++)
        #pragma unroll
        for (int i = 0; i < 4; i++) D2[nt][i] = 0.0f;
    float rsum[2] = {0.0f, 0.0f};
    float mrow0 = -1e30f, mrow1 = -1e30f;

    for (int jt = 0; jt < 16; jt++) {
        const uint32_t cur = STG + (uint32_t)(jt & 1) * SSZ;

        if (jt < 15) {
            const uint32_t nxt = STG + (uint32_t)((jt + 1) & 1) * SSZ;
            #pragma unroll
            for (int t = 0; t < 2; t++) {
                int flat = tid + t * NTHREADS;
                uint32_t c = (uint32_t)(flat >> 3), ch = (uint32_t)(flat & 7);
                uint32_t dst = c * 128u + ((ch * 16u) ^ ((c & 7u) << 4));
                unsigned so = pbo + c * 1024u + (unsigned)(jt + 1) * 64u + ch * 8u;
                cpa16(smb + nxt + JHIo + dst, g_JHi + so);
                cpa16(smb + nxt + JLOo + dst, g_JLo + so);
                cpa16(smb + nxt + VHo  + dst, g_VH  + so);
            }
            CP_COMMIT();
        }

        // ---------- GEMM1: S̃[16 x 32] (log2 domain) fp16 3-pass ----------
        float S[4][4];
        #pragma unroll
        for (int nt = 0; nt < 4; nt++)
            #pragma unroll
            for (int i = 0; i < 4; i++) S[nt][i] = 0.0f;

        #pragma unroll
        for (int ks = 0; ks < 4; ks++) {
            uint32_t jrow = (uint32_t)(ks * 16) * 128u + bRowJ;
            #pragma unroll
            for (int ntp = 0; ntp < 2; ntp++) {
                uint32_t bh[4], bl[4];
                uint32_t bcol = ((uint32_t)((j0 + ntp * 16) * 2) + bColJ) ^ xorl;
                ldsm4t(bh, smb + cur + JHIo + jrow + bcol);
                ldsm4t(bl, smb + cur + JLOo + jrow + bcol);
                #pragma unroll
                for (int q = 0; q < 2; q++) {
                    int nt = 2 * ntp + q;
                    mma_f16(S[nt], kfh[ks], bh[2 * q], bh[2 * q + 1]);
                    mma_f16(S[nt], kfh[ks], bl[2 * q], bl[2 * q + 1]);
                    mma_f16(S[nt], kfl[ks], bh[2 * q], bh[2 * q + 1]);
                }
            }
        }

        // ---------- online softmax (log2 domain): row max, conditional rescale ----------
        float mx0 = -1e30f, mx1 = -1e30f;
        #pragma unroll
        for (int nt = 0; nt < 4; nt++) {
            mx0 = fmaxf(mx0, fmaxf(S[nt][0], S[nt][1]));
            mx1 = fmaxf(mx1, fmaxf(S[nt][2], S[nt][3]));
        }
        mx0 = fmaxf(mx0, __shfl_xor_sync(0xffffffffu, mx0, 1));
        mx0 = fmaxf(mx0, __shfl_xor_sync(0xffffffffu, mx0, 2));
        mx1 = fmaxf(mx1, __shfl_xor_sync(0xffffffffu, mx1, 1));
        mx1 = fmaxf(mx1, __shfl_xor_sync(0xffffffffu, mx1, 2));
        bool changed = (mx0 > mrow0) || (mx1 > mrow1);
        if (__any_sync(0xffffffffu, changed)) {
            float nm0 = fmaxf(mrow0, mx0), nm1 = fmaxf(mrow1, mx1);
            float a0 = ex2f(mrow0 - nm0), a1 = ex2f(mrow1 - nm1);
            mrow0 = nm0; mrow1 = nm1;
            rsum[0] *= a0; rsum[1] *= a1;
            #pragma unroll
            for (int nt = 0; nt < 8; nt++) {
                D2[nt][0] *= a0; D2[nt][1] *= a0;
                D2[nt][2] *= a1; D2[nt][3] *= a1;
            }
        }

        uint32_t phi[2][4];
        #pragma unroll
        for (int g = 0; g < 2; g++)
            #pragma unroll
            for (int q = 0; q < 2; q++) {
                const float* s = S[2 * g + q];
                float p0 = ex2f(s[0] - mrow0), p1 = ex2f(s[1] - mrow0);
                float p2 = ex2f(s[2] - mrow1), p3 = ex2f(s[3] - mrow1);
                rsum[0] += p0 + p1;
                rsum[1] += p2 + p3;
                phi[g][2 * q]     = u32h2(__floats2half2_rn(p0, p1));
                phi[g][2 * q + 1] = u32h2(__floats2half2_rn(p2, p3));
            }

        // ---------- GEMM2: D2 += P x V^T, fp16 1-pass ----------
        #pragma unroll
        for (int nt = 0; nt < 8; nt++) {
            uint32_t vh[4];
            uint32_t vr = (uint32_t)(nt * 8) * 128u + vRow;
            ldsm4(vh, smb + cur + VHo + vr + vcol);
            #pragma unroll
            for (int g = 0; g < 2; g++)
                mma_f16(D2[nt], phi[g], vh[2 * g], vh[2 * g + 1]);
        }

        if (jt < 15) CP_WAIT0();
        __syncthreads();
    }

    // ---------- Epilogue: reconcile maxes across the two j-half warps ----------
    const int r = m0 + (lane >> 2);
    if ((lane & 3) == 0) {
        msm[wn * 64 + r]     = mrow0;
        msm[wn * 64 + r + 8] = mrow1;
    }
    __syncthreads();
    {
        float M0 = fmaxf(msm[r], msm[64 + r]);
        float M1 = fmaxf(msm[r + 8], msm[64 + r + 8]);
        float s0 = ex2f(mrow0 - M0), s1 = ex2f(mrow1 - M1);
        rsum[0] *= s0; rsum[1] *= s1;
        #pragma unroll
        for (int nt = 0; nt < 8; nt++) {
            D2[nt][0] *= s0; D2[nt][1] *= s0;
            D2[nt][2] *= s1; D2[nt][3] *= s1;
        }
    }

    #pragma unroll
    for (int rr = 0; rr < 2; rr++) {
        float v = rsum[rr];
        v += __shfl_xor_sync(0xffffffffu, v, 1);
        v += __shfl_xor_sync(0xffffffffu, v, 2);
        if ((lane & 3) == 0)
            lred[wn * 64 + m0 + rr * 8 + (lane >> 2)] = v;
    }
    __syncthreads();
    if (tid < 64) lred[128 + tid] = 1.0f / (lred[tid] + lred[64 + tid]);

    if (wn == 0) {
        #pragma unroll
        for (int nt = 0; nt < 8; nt++) {
            int c0 = nt * 8 + 2 * (lane & 3);
            int rw = m0 + (lane >> 2);
            ostage[c0 * 64 + rw]           = D2[nt][0];
            ostage[(c0 + 1) * 64 + rw]     = D2[nt][1];
            ostage[c0 * 64 + rw + 8]       = D2[nt][2];
            ostage[(c0 + 1) * 64 + rw + 8] = D2[nt][3];
        }
    }
    __syncthreads();
    if (wn == 1) {
        #pragma unroll
        for (int nt = 0; nt < 8; nt++) {
            int c0 = nt * 8 + 2 * (lane & 3);
            int rw = m0 + (lane >> 2);
            ostage[c0 * 64 + rw]           += D2[nt][0];
            ostage[(c0 + 1) * 64 + rw]     += D2[nt][1];
            ostage[c0 * 64 + rw + 8]       += D2[nt][2];
            ostage[(c0 + 1) * 64 + rw + 8] += D2[nt][3];
        }
    }
    __syncthreads();

    #pragma unroll
    for (int t = 0; t < 4; t++) {
        int flat = tid + t * NTHREADS;
        int c = flat >> 4, k4 = flat & 15;
        float4 v  = *(float4*)(ostage + c * 64 + k4 * 4);
        float4 iv = *(float4*)(lred + 128 + k4 * 4);
        v.x *= iv.x; v.y *= iv.y; v.z *= iv.z; v.w *= iv.w;
        *(float4*)(Og + pbo + (unsigned)c * 1024u + kbase + (unsigned)k4 * 4u) = v;
    }
}

extern "C" void kernel_launch(void* const* d_in, const int* in_sizes, int n_in,
                              void* d_out, int out_size) {
    const float* Kg = (const float*)d_in[0];
    const float* Jg = (const float*)d_in[1];
    const float* Vg = (const float*)d_in[2];
    float* Og = (float*)d_out;

    prep_kernel<<<5120, 256>>>(Kg, Jg, Vg);

    cudaFuncSetAttribute(attn_mma_kernel,
                         cudaFuncAttributeMaxDynamicSharedMemorySize, SMEM_BYTES);
    dim3 grid(16, 64);
    attn_mma_kernel<<<grid, NTHREADS, SMEM_BYTES>>>(Og);
}

// round 12
// speedup vs baseline: 1.7094x; 1.0023x over previous
#include <cuda_runtime.h>
#include <cuda_fp16.h>
#include <cuda_bf16.h>
#include <cstdint>

// self_attention_9225589752302 — round 11: 3-stage cp.async (wait_group 1),
// hoisted copy addressing, higher-MLP prep.
// GEMM1 fp16 hi/lo 3-pass (K^T cached in regs, log2 domain), GEMM2 fp16 1-pass.
// grid (16 k-tiles, 64 batches), 256 thr, 2 CTAs/SM.

#define NTHREADS 256
#define LOG2E 1.4426950408889634f

// ---- global scratch ----
__device__ __half g_KtHi[4194304];   // [pb][k=1024][c=64], pre-scaled by log2e
__device__ __half g_KtLo[4194304];
__device__ __half g_JHi [4194304];   // [pb][c=64][j=1024]
__device__ __half g_JLo [4194304];
__device__ __half g_VH  [4194304];   // [pb][c=64][j=1024] single fp16

// ---- smem layout: K 16KB | 3 stages x 24KB | LRED ----
#define KHIo 0u
#define KLOo 8192u
#define STG  16384u
#define SSZ  24576u
#define JHIo 0u
#define JLOo 8192u
#define VHo  16384u
#define LRED (16384u + 3u * 24576u)     // 90112
#define SMEM_BYTES (LRED + 1536u)       // 91648
#define OSTAGE 0u

static __device__ __forceinline__ uint32_t smem_u32(const void* p) {
    uint32_t a;
    asm("{ .reg .u64 t; cvta.to.shared.u64 t, %1; cvt.u32.u64 %0, t; }" : "=r"(a) : "l"(p));
    return a;
}
static __device__ __forceinline__ float ex2f(float x) {
    float r;
    asm("ex2.approx.ftz.f32 %0, %1;" : "=f"(r) : "f"(x));
    return r;
}
static __device__ __forceinline__ void cpa16(uint32_t dst, const void* src) {
    asm volatile("cp.async.cg.shared.global [%0], [%1], 16;" :: "r"(dst), "l"(src));
}
#define CP_COMMIT() asm volatile("cp.async.commit_group;" ::: "memory")
#define CP_WAIT1()  asm volatile("cp.async.wait_group 1;" ::: "memory")
#define CP_WAIT0()  asm volatile("cp.async.wait_group 0;" ::: "memory")

static __device__ __forceinline__ void ldsm4(uint32_t r[4], uint32_t a) {
    asm volatile("ldmatrix.sync.aligned.m8n8.x4.shared.b16 {%0,%1,%2,%3}, [%4];"
        : "=r"(r[0]), "=r"(r[1]), "=r"(r[2]), "=r"(r[3]) : "r"(a));
}
static __device__ __forceinline__ void ldsm4t(uint32_t r[4], uint32_t a) {
    asm volatile("ldmatrix.sync.aligned.m8n8.x4.trans.shared.b16 {%0,%1,%2,%3}, [%4];"
        : "=r"(r[0]), "=r"(r[1]), "=r"(r[2]), "=r"(r[3]) : "r"(a));
}
static __device__ __forceinline__ void mma_f16(float d[4], const uint32_t a[4], uint32_t b0, uint32_t b1) {
    asm("mma.sync.aligned.m16n8k16.row.col.f32.f16.f16.f32 "
        "{%0,%1,%2,%3}, {%4,%5,%6,%7}, {%8,%9}, {%0,%1,%2,%3};"
        : "+f"(d[0]), "+f"(d[1]), "+f"(d[2]), "+f"(d[3])
        : "r"(a[0]), "r"(a[1]), "r"(a[2]), "r"(a[3]), "r"(b0), "r"(b1));
}
static __device__ __forceinline__ uint32_t u32h2(__half2 h) { return *(uint32_t*)&h; }

// ---- merged prep: blocks [0,2048) split J/V (2 float4/thr); [2048,3072) K^T*log2e ----
__global__ __launch_bounds__(256)
void prep_kernel(const float* __restrict__ K, const float* __restrict__ J,
                 const float* __restrict__ V) {
    __shared__ float s[64][65];
    const int tid = threadIdx.x;
    const unsigned b = blockIdx.x;
    if (b < 2048u) {
        #pragma unroll
        for (int u = 0; u < 2; u++) {
            unsigned f = b * 512u + (unsigned)tid + (unsigned)u * 256u;
            float4 jv = ((const float4*)J)[f];
            float4 vv = ((const float4*)V)[f];
            __half2 h0 = __floats2half2_rn(jv.x, jv.y), h1 = __floats2half2_rn(jv.z, jv.w);
            float2 a0 = __half22float2(h0), a1 = __half22float2(h1);
            __half2 l0 = __floats2half2_rn(jv.x - a0.x, jv.y - a0.y);
            __half2 l1 = __floats2half2_rn(jv.z - a1.x, jv.w - a1.y);
            ((__half2*)g_JHi)[f * 2] = h0; ((__half2*)g_JHi)[f * 2 + 1] = h1;
            ((__half2*)g_JLo)[f * 2] = l0; ((__half2*)g_JLo)[f * 2 + 1] = l1;
            ((__half2*)g_VH)[f * 2]     = __floats2half2_rn(vv.x, vv.y);
            ((__half2*)g_VH)[f * 2 + 1] = __floats2half2_rn(vv.z, vv.w);
        }
    } else {
        const unsigned bb = b - 2048u;
        const unsigned base = (bb >> 4) * 65536u;
        const unsigned k0 = (bb & 15u) * 64u;
        #pragma unroll
        for (int t = 0; t < 16; t++) {
            int flat = tid + t * 256;
            int c = flat >> 6, k = flat & 63;
            s[c][k] = K[base + (unsigned)c * 1024u + k0 + k] * LOG2E;
        }
        __syncthreads();
        #pragma unroll
        for (int t = 0; t < 16; t++) {
            int flat = tid + t * 256;
            int k = flat >> 6, c = flat & 63;
            float x = s[c][k];
            __half h = __float2half_rn(x);
            __half l = __float2half_rn(x - __half2float(h));
            unsigned o = base + (k0 + (unsigned)k) * 64u + (unsigned)c;
            g_KtHi[o] = h;
            g_KtLo[o] = l;
        }
    }
}

// ---- main kernel ----
__global__ __launch_bounds__(NTHREADS, 2)
void attn_mma_kernel(float* __restrict__ Og) {
    extern __shared__ char smem[];
    const uint32_t smb = smem_u32(smem);
    float* lred  = (float*)(smem + LRED);
    float* msm   = lred + 192;
    float* ostage = (float*)(smem + OSTAGE);

    const int tid  = threadIdx.x;
    const int lane = tid & 31;
    const int wid  = tid >> 5;
    const int wm   = wid & 3;
    const int wn   = wid >> 2;
    const int m0   = wm * 16;
    const int j0   = wn * 32;
    const unsigned pbo   = (unsigned)blockIdx.y * 65536u;
    const unsigned kbase = (unsigned)blockIdx.x * 64u;

    // hoisted copy addressing: 2 chunks per thread
    uint32_t dstoff[2];
    unsigned srcoff[2];
    #pragma unroll
    for (int t = 0; t < 2; t++) {
        int flat = tid + t * NTHREADS;
        uint32_t c = (uint32_t)(flat >> 3), ch = (uint32_t)(flat & 7);
        dstoff[t] = c * 128u + ((ch * 16u) ^ ((c & 7u) << 4));
        srcoff[t] = pbo + c * 1024u + ch * 8u;
    }

    // ---------- prologue: K tile + stages 0,1 ----------
    #pragma unroll
    for (int t = 0; t < 2; t++) {
        int flat = tid + t * NTHREADS;
        uint32_t k = (uint32_t)(flat >> 3), ch = (uint32_t)(flat & 7);
        uint32_t dst = k * 128u + ((ch * 16u) ^ ((k & 7u) << 4));
        unsigned so = pbo + (kbase + k) * 64u + ch * 8u;
        cpa16(smb + KHIo + dst, g_KtHi + so);
        cpa16(smb + KLOo + dst, g_KtLo + so);
    }
    #pragma unroll
    for (int t = 0; t < 2; t++) {
        cpa16(smb + STG + JHIo + dstoff[t], g_JHi + srcoff[t]);
        cpa16(smb + STG + JLOo + dstoff[t], g_JLo + srcoff[t]);
        cpa16(smb + STG + VHo  + dstoff[t], g_VH  + srcoff[t]);
    }
    CP_COMMIT();
    #pragma unroll
    for (int t = 0; t < 2; t++) {
        cpa16(smb + STG + SSZ + JHIo + dstoff[t], g_JHi + srcoff[t] + 64u);
        cpa16(smb + STG + SSZ + JLOo + dstoff[t], g_JLo + srcoff[t] + 64u);
        cpa16(smb + STG + SSZ + VHo  + dstoff[t], g_VH  + srcoff[t] + 64u);
    }
    CP_COMMIT();
    CP_WAIT1();   // K + stage0 complete
    __syncthreads();

    // lane-constant address pieces
    const uint32_t xorl  = (uint32_t)(lane & 7) << 4;
    const uint32_t aRow0 = (uint32_t)(m0 + (lane & 15)) * 128u;
    const uint32_t aColH = (uint32_t)((lane >> 4) << 4);
    const uint32_t bRowJ = (uint32_t)((lane & 15)) * 128u;
    const uint32_t bColJ = (uint32_t)((lane >> 4) << 4);
    const uint32_t vRow  = (uint32_t)(lane & 7) * 128u;
    const uint32_t vColH = (uint32_t)((lane >> 3) << 4);
    const uint32_t vcol  = ((uint32_t)(j0 * 2) + vColH) ^ xorl;

    // ---------- cache K fragments in registers ----------
    uint32_t kfh[4][4], kfl[4][4];
    #pragma unroll
    for (int ks = 0; ks < 4; ks++) {
        uint32_t acol = ((uint32_t)(ks * 32) + aColH) ^ xorl;
        ldsm4(kfh[ks], smb + KHIo + aRow0 + acol);
        ldsm4(kfl[ks], smb + KLOo + aRow0 + acol);
    }

    float D2[8][4];
    #pragma unroll
    for (int nt = 0; nt < 8; nt++)
        #pragma unroll
        for (int i = 0; i < 4; i++) D2[nt][i] = 0.0f;
    float rsum[2] = {0.0f, 0.0f};
    float mrow0 = -1e30f, mrow1 = -1e30f;

    uint32_t curst = 0;   // stage index of current tile

    for (int jt = 0; jt < 16; jt++) {
        const uint32_t cur = STG + curst * SSZ;

        // issue copies for jt+2 into stage (curst+2)%3
        if (jt < 14) {
            uint32_t ns = curst + 2u; if (ns >= 3u) ns -= 3u;
            const uint32_t nxt = STG + ns * SSZ;
            unsigned go = (unsigned)(jt + 2) * 64u;
            #pragma unroll
            for (int t = 0; t < 2; t++) {
                cpa16(smb + nxt + JHIo + dstoff[t], g_JHi + srcoff[t] + go);
                cpa16(smb + nxt + JLOo + dstoff[t], g_JLo + srcoff[t] + go);
                cpa16(smb + nxt + VHo  + dstoff[t], g_VH  + srcoff[t] + go);
            }
            CP_COMMIT();
        }

        // ---------- GEMM1: S̃[16 x 32] (log2 domain) fp16 3-pass ----------
        float S[4][4];
        #pragma unroll
        for (int nt = 0; nt < 4; nt++)
            #pragma unroll
            for (int i = 0; i < 4; i++) S[nt][i] = 0.0f;

        #pragma unroll
        for (int ks = 0; ks < 4; ks++) {
            uint32_t jrow = (uint32_t)(ks * 16) * 128u + bRowJ;
            #pragma unroll
            for (int ntp = 0; ntp < 2; ntp++) {
                uint32_t bh[4], bl[4];
                uint32_t bcol = ((uint32_t)((j0 + ntp * 16) * 2) + bColJ) ^ xorl;
                ldsm4t(bh, smb + cur + JHIo + jrow + bcol);
                ldsm4t(bl, smb + cur + JLOo + jrow + bcol);
                #pragma unroll
                for (int q = 0; q < 2; q++) {
                    int nt = 2 * ntp + q;
                    mma_f16(S[nt], kfh[ks], bh[2 * q], bh[2 * q + 1]);
                    mma_f16(S[nt], kfh[ks], bl[2 * q], bl[2 * q + 1]);
                    mma_f16(S[nt], kfl[ks], bh[2 * q], bh[2 * q + 1]);
                }
            }
        }

        // ---------- online softmax (log2 domain) ----------
        float mx0 = -1e30f, mx1 = -1e30f;
        #pragma unroll
        for (int nt = 0; nt < 4; nt++) {
            mx0 = fmaxf(mx0, fmaxf(S[nt][0], S[nt][1]));
            mx1 = fmaxf(mx1, fmaxf(S[nt][2], S[nt][3]));
        }
        mx0 = fmaxf(mx0, __shfl_xor_sync(0xffffffffu, mx0, 1));
        mx0 = fmaxf(mx0, __shfl_xor_sync(0xffffffffu, mx0, 2));
        mx1 = fmaxf(mx1, __shfl_xor_sync(0xffffffffu, mx1, 1));
        mx1 = fmaxf(mx1, __shfl_xor_sync(0xffffffffu, mx1, 2));
        bool changed = (mx0 > mrow0) || (mx1 > mrow1);
        if (__any_sync(0xffffffffu, changed)) {
            float nm0 = fmaxf(mrow0, mx0), nm1 = fmaxf(mrow1, mx1);
            float a0 = ex2f(mrow0 - nm0), a1 = ex2f(mrow1 - nm1);
            mrow0 = nm0; mrow1 = nm1;
            rsum[0] *= a0; rsum[1] *= a1;
            #pragma unroll
            for (int nt = 0; nt < 8; nt++) {
                D2[nt][0] *= a0; D2[nt][1] *= a0;
                D2[nt][2] *= a1; D2[nt][3] *= a1;
            }
        }

        uint32_t phi[2][4];
        #pragma unroll
        for (int g = 0; g < 2; g++)
            #pragma unroll
            for (int q = 0; q < 2; q++) {
                const float* s = S[2 * g + q];
                float p0 = ex2f(s[0] - mrow0), p1 = ex2f(s[1] - mrow0);
                float p2 = ex2f(s[2] - mrow1), p3 = ex2f(s[3] - mrow1);
                rsum[0] += p0 + p1;
                rsum[1] += p2 + p3;
                phi[g][2 * q]     = u32h2(__floats2half2_rn(p0, p1));
                phi[g][2 * q + 1] = u32h2(__floats2half2_rn(p2, p3));
            }

        // ---------- GEMM2: D2 += P x V^T, fp16 1-pass ----------
        #pragma unroll
        for (int nt = 0; nt < 8; nt++) {
            uint32_t vh[4];
            uint32_t vr = (uint32_t)(nt * 8) * 128u + vRow;
            ldsm4(vh, smb + cur + VHo + vr + vcol);
            #pragma unroll
            for (int g = 0; g < 2; g++)
                mma_f16(D2[nt], phi[g], vh[2 * g], vh[2 * g + 1]);
        }

        if (jt < 14) { CP_WAIT1(); }
        else if (jt == 14) { CP_WAIT0(); }
        __syncthreads();
        curst = (curst == 2u) ? 0u : curst + 1u;
    }

    // ---------- Epilogue: reconcile maxes across the two j-half warps ----------
    const int r = m0 + (lane >> 2);
    if ((lane & 3) == 0) {
        msm[wn * 64 + r]     = mrow0;
        msm[wn * 64 + r + 8] = mrow1;
    }
    __syncthreads();
    {
        float M0 = fmaxf(msm[r], msm[64 + r]);
        float M1 = fmaxf(msm[r + 8], msm[64 + r + 8]);
        float s0 = ex2f(mrow0 - M0), s1 = ex2f(mrow1 - M1);
        rsum[0] *= s0; rsum[1] *= s1;
        #pragma unroll
        for (int nt = 0; nt < 8; nt++) {
            D2[nt][0] *= s0; D2[nt][1] *= s0;
            D2[nt][2] *= s1; D2[nt][3] *= s1;
        }
    }

    #pragma unroll
    for (int rr = 0; rr < 2; rr++) {
        float v = rsum[rr];
        v += __shfl_xor_sync(0xffffffffu, v, 1);
        v += __shfl_xor_sync(0xffffffffu, v, 2);
        if ((lane & 3) == 0)
            lred[wn * 64 + m0 + rr * 8 + (lane >> 2)] = v;
    }
    __syncthreads();
    if (tid < 64) lred[128 + tid] = 1.0f / (lred[tid] + lred[64 + tid]);

    if (wn == 0) {
        #pragma unroll
        for (int nt = 0; nt < 8; nt++) {
            int c0 = nt * 8 + 2 * (lane & 3);
            int rw = m0 + (lane >> 2);
            ostage[c0 * 64 + rw]           = D2[nt][0];
            ostage[(c0 + 1) * 64 + rw]     = D2[nt][1];
            ostage[c0 * 64 + rw + 8]       = D2[nt][2];
            ostage[(c0 + 1) * 64 + rw + 8] = D2[nt][3];
        }
    }
    __syncthreads();
    if (wn == 1) {
        #pragma unroll
        for (int nt = 0; nt < 8; nt++) {
            int c0 = nt * 8 + 2 * (lane & 3);
            int rw = m0 + (lane >> 2);
            ostage[c0 * 64 + rw]           += D2[nt][0];
            ostage[(c0 + 1) * 64 + rw]     += D2[nt][1];
            ostage[c0 * 64 + rw + 8]       += D2[nt][2];
            ostage[(c0 + 1) * 64 + rw + 8] += D2[nt][3];
        }
    }
    __syncthreads();

    #pragma unroll
    for (int t = 0; t < 4; t++) {
        int flat = tid + t * NTHREADS;
        int c = flat >> 4, k4 = flat & 15;
        float4 v  = *(float4*)(ostage + c * 64 + k4 * 4);
        float4 iv = *(float4*)(lred + 128 + k4 * 4);
        v.x *= iv.x; v.y *= iv.y; v.z *= iv.z; v.w *= iv.w;
        *(float4*)(Og + pbo + (unsigned)c * 1024u + kbase + (unsigned)k4 * 4u) = v;
    }
}

extern "C" void kernel_launch(void* const* d_in, const int* in_sizes, int n_in,
                              void* d_out, int out_size) {
    const float* Kg = (const float*)d_in[0];
    const float* Jg = (const float*)d_in[1];
    const float* Vg = (const float*)d_in[2];
    float* Og = (float*)d_out;

    prep_kernel<<<3072, 256>>>(Kg, Jg, Vg);

    cudaFuncSetAttribute(attn_mma_kernel,
                         cudaFuncAttributeMaxDynamicSharedMemorySize, SMEM_BYTES);
    dim3 grid(16, 64);
    attn_mma_kernel<<<grid, NTHREADS, SMEM_BYTES>>>(Og);
}